// round 7
// baseline (speedup 1.0000x reference)
#include <cuda_runtime.h>
#include <math.h>

#define BB  2
#define HH  12
#define LL  1024
#define DD  768
#define DHH 64
#define NBH (BB*HH)
#define SSTR 68
#define ESTR 132

// Scratch (static __device__ arrays; no allocations anywhere)
__device__ float g_q [NBH*LL*DHH];        //  6.3 MB  [b,h,l,dh]
__device__ float g_k [NBH*LL*DHH];
__device__ float g_v [NBH*LL*DHH];
__device__ float g_qw[5*NBH*LL*DHH];      // 31.5 MB  [i,b,h,l,e]
__device__ float g_s [NBH*LL*LL];         // 100.7 MB [b,h,l,r]

// ---------------------------------------------------------------------------
// tf32 mma helpers
// ---------------------------------------------------------------------------
__device__ __forceinline__ unsigned f2tf(float v) {
    unsigned r; asm("cvt.rna.tf32.f32 %0, %1;" : "=r"(r) : "f"(v)); return r;
}
__device__ __forceinline__ float f2tff(float v) { return __uint_as_float(f2tf(v)); }

__device__ __forceinline__ void mma8(float* c, const unsigned* a, const unsigned* b) {
    asm volatile("mma.sync.aligned.m16n8k8.row.col.f32.tf32.tf32.f32 "
        "{%0,%1,%2,%3}, {%4,%5,%6,%7}, {%8,%9}, {%0,%1,%2,%3};"
        : "+f"(c[0]), "+f"(c[1]), "+f"(c[2]), "+f"(c[3])
        : "r"(a[0]), "r"(a[1]), "r"(a[2]), "r"(a[3]), "r"(b[0]), "r"(b[1]));
}

// ---------------------------------------------------------------------------
// K1: projection  out = X @ W + bias, stored as [B,H,L,DH]  (FFMA, ~40us each)
// ---------------------------------------------------------------------------
__global__ __launch_bounds__(256) void proj_kernel(
    const float* __restrict__ X, const float* __restrict__ W,
    const float* __restrict__ bias, int which)
{
    __shared__ float As[16][68];   // [k][m]
    __shared__ float Bs[16][68];   // [k][n]
    float* outp = (which == 0) ? g_q : (which == 1) ? g_k : g_v;

    const int tid = threadIdx.x;
    const int tx = tid & 15, ty = tid >> 4;
    const int n0 = blockIdx.x * 64;
    const int m0 = blockIdx.y * 64;
    const int a_m = tid >> 2,  a_k4 = (tid & 3) << 2;
    const int b_k = tid >> 4,  b_n4 = (tid & 15) << 2;

    float acc[4][4] = {};
    for (int k0 = 0; k0 < DD; k0 += 16) {
        float4 av = *(const float4*)&X[(m0 + a_m) * DD + k0 + a_k4];
        float4 bv = *(const float4*)&W[(k0 + b_k) * DD + n0 + b_n4];
        __syncthreads();
        As[a_k4 + 0][a_m] = av.x;
        As[a_k4 + 1][a_m] = av.y;
        As[a_k4 + 2][a_m] = av.z;
        As[a_k4 + 3][a_m] = av.w;
        *(float4*)&Bs[b_k][b_n4] = bv;
        __syncthreads();
        #pragma unroll
        for (int kk = 0; kk < 16; kk++) {
            float4 a = *(const float4*)&As[kk][ty << 2];
            float4 b = *(const float4*)&Bs[kk][tx << 2];
            float aa[4] = {a.x, a.y, a.z, a.w};
            float bb[4] = {b.x, b.y, b.z, b.w};
            #pragma unroll
            for (int i = 0; i < 4; i++)
                #pragma unroll
                for (int j = 0; j < 4; j++)
                    acc[i][j] += aa[i] * bb[j];
        }
    }
    const int h = blockIdx.x;              // n-tile index == head (DH==64)
    float bb4[4];
    #pragma unroll
    for (int j = 0; j < 4; j++) bb4[j] = bias[n0 + (tx << 2) + j];
    #pragma unroll
    for (int i = 0; i < 4; i++) {
        int row = m0 + (ty << 2) + i;
        int b = row >> 10, l = row & 1023;
        float4 o;
        o.x = acc[i][0] + bb4[0];
        o.y = acc[i][1] + bb4[1];
        o.z = acc[i][2] + bb4[2];
        o.w = acc[i][3] + bb4[3];
        *(float4*)&outp[((b * HH + h) * LL + l) * DHH + (tx << 2)] = o;
    }
}

// ---------------------------------------------------------------------------
// K2: qw[i,b,h,l,:] = q[b,h,l,:] @ ssan_w[i,h]   (FFMA, 35us)
// ---------------------------------------------------------------------------
__global__ __launch_bounds__(256) void qw_kernel(const float* __restrict__ ssan_w)
{
    __shared__ float qsT[64][68];   // [d][l]
    __shared__ float ws [64][68];   // [d][e]
    const int tid = threadIdx.x;
    const int tx = tid & 15, ty = tid >> 4;
    const int l0 = blockIdx.x * 64;
    const int h  = blockIdx.y;
    const int z  = blockIdx.z;           // i*B + b
    const int ii = z >> 1, b = z & 1;

    const float* qb = g_q + ((b * HH + h) * LL) * DHH;
    const float* wb = ssan_w + (ii * HH + h) * DHH * DHH;

    for (int idx = tid; idx < 1024; idx += 256) {
        int lt = idx >> 4, d4 = (idx & 15) << 2;
        float4 v = *(const float4*)&qb[(l0 + lt) * DHH + d4];
        qsT[d4 + 0][lt] = v.x;
        qsT[d4 + 1][lt] = v.y;
        qsT[d4 + 2][lt] = v.z;
        qsT[d4 + 3][lt] = v.w;
        int d = idx >> 4, e4 = (idx & 15) << 2;
        *(float4*)&ws[d][e4] = *(const float4*)&wb[d * DHH + e4];
    }
    __syncthreads();

    float acc[4][4] = {};
    #pragma unroll 4
    for (int d = 0; d < 64; d++) {
        float4 q = *(const float4*)&qsT[d][ty << 2];
        float4 w = *(const float4*)&ws [d][tx << 2];
        float qq[4] = {q.x, q.y, q.z, q.w};
        float ww[4] = {w.x, w.y, w.z, w.w};
        #pragma unroll
        for (int i = 0; i < 4; i++)
            #pragma unroll
            for (int j = 0; j < 4; j++)
                acc[i][j] += qq[i] * ww[j];
    }
    float* ob = g_qw + (((ii * BB + b) * HH + h) * LL) * DHH;
    #pragma unroll
    for (int i = 0; i < 4; i++) {
        float4 o = {acc[i][0], acc[i][1], acc[i][2], acc[i][3]};
        *(float4*)&ob[(l0 + (ty << 2) + i) * DHH + (tx << 2)] = o;
    }
}

// ---------------------------------------------------------------------------
// K3: fused score assembly via mma.sync tf32.
//   s = (q·k + (q+k)·e[l-r]) / 8 + mask + sum_i (qW_i·k + abs_i) * struct_i
// grid (16 rtiles, 16 ltiles, B*H), block 256 (8 warps), 64x64 output tile.
// e-term via two 64x127x64 band GEMMs into SMEM + diagonal gather.
// ---------------------------------------------------------------------------
extern __shared__ float s_mem[];
__global__ __launch_bounds__(256, 1) void scores_mma_kernel(
    const float* __restrict__ amask, const float* __restrict__ structm,
    const float* __restrict__ dist_emb, const float* __restrict__ abs_bias)
{
    float* Qs  = s_mem;                  // 64*68   (tf32 bits)
    float* Ks  = Qs + 64 * SSTR;         // 64*68
    float* Es  = Ks + 64 * SSTR;         // 128*68  (band, row 127 zero)
    float* Wb0 = Es + 128 * SSTR;        // 64*68
    float* Wb1 = Wb0 + 64 * SSTR;        // 64*68
    float* QEs = Wb1 + 64 * SSTR;        // 64*132  fp32 qe band result
    float* KEs = QEs + 64 * ESTR;        // 64*132  fp32 ke band result

    const int tid = threadIdx.x;
    const int lane = tid & 31, w = tid >> 5;
    const int r0 = blockIdx.x * 64;
    const int l0 = blockIdx.y * 64;
    const int bh = blockIdx.z;
    const int b = bh / HH, h = bh % HH;

    const float* qb = g_q + (size_t)bh * LL * DHH;
    const float* kb = g_k + (size_t)bh * LL * DHH;

    // ---- phase 0: stage Q, K, E band (cvt to tf32), prefetch QW0 --------
    const int lt  = tid >> 2;            // 0..63
    const int d16 = (tid & 3) << 4;      // 0,16,32,48
    const int base_m = l0 - r0 + 960;
    const int er = tid >> 1;             // 0..127
    const int ed = (tid & 1) * 32;

    float4 qreg[4], kreg[4], wreg[4], ereg[8];
    #pragma unroll
    for (int c = 0; c < 4; c++) {
        qreg[c] = *(const float4*)&qb[(l0 + lt) * DHH + d16 + c * 4];
        kreg[c] = *(const float4*)&kb[(r0 + lt) * DHH + d16 + c * 4];
    }
    {
        const float* wb = g_qw + ((size_t)(0 * BB + b) * HH + h) * LL * DHH;
        #pragma unroll
        for (int c = 0; c < 4; c++)
            wreg[c] = *(const float4*)&wb[(l0 + lt) * DHH + d16 + c * 4];
    }
    #pragma unroll
    for (int c = 0; c < 8; c++)
        ereg[c] = (er < 127) ? *(const float4*)&dist_emb[(base_m + er) * DHH + ed + c * 4]
                             : make_float4(0.f, 0.f, 0.f, 0.f);

    #pragma unroll
    for (int c = 0; c < 4; c++) {
        float4 v = qreg[c];
        float4 o = {f2tff(v.x), f2tff(v.y), f2tff(v.z), f2tff(v.w)};
        *(float4*)&Qs[lt * SSTR + d16 + c * 4] = o;
        v = kreg[c];
        float4 o2 = {f2tff(v.x), f2tff(v.y), f2tff(v.z), f2tff(v.w)};
        *(float4*)&Ks[lt * SSTR + d16 + c * 4] = o2;
    }
    #pragma unroll
    for (int c = 0; c < 8; c++) {
        float4 v = ereg[c];
        float4 o = {f2tff(v.x), f2tff(v.y), f2tff(v.z), f2tff(v.w)};
        *(float4*)&Es[er * SSTR + ed + c * 4] = o;
    }
    __syncthreads();

    const int mrow = (w & 3) * 16;       // l sub-tile for this warp
    const int ncol = (w >> 2) * 32;      // r sub-range for main GEMMs
    const int nh   = (w >> 2) * 64;      // band sub-range for e GEMMs
    const int lq = lane >> 2, lr = lane & 3;

    // ---- e-band GEMMs: qe = Q @ E^T, ke = K @ E^T (each 64x128x64) ------
    {
        float ea[32];
        #pragma unroll
        for (int z = 0; z < 32; z++) ea[z] = 0.f;
        #pragma unroll
        for (int k0 = 0; k0 < 8; k0++) {
            unsigned a[4];
            int ar = (mrow + lq) * SSTR + k0 * 8 + lr;
            a[0] = __float_as_uint(Qs[ar]);
            a[1] = __float_as_uint(Qs[ar + 8 * SSTR]);
            a[2] = __float_as_uint(Qs[ar + 4]);
            a[3] = __float_as_uint(Qs[ar + 8 * SSTR + 4]);
            #pragma unroll
            for (int nb = 0; nb < 8; nb++) {
                unsigned bf[2];
                int br = (nh + nb * 8 + lq) * SSTR + k0 * 8 + lr;
                bf[0] = __float_as_uint(Es[br]);
                bf[1] = __float_as_uint(Es[br + 4]);
                mma8(ea + nb * 4, a, bf);
            }
        }
        #pragma unroll
        for (int nb = 0; nb < 8; nb++) {
            int rr = mrow + lq;
            int cc = nh + nb * 8 + lr * 2;
            *(float2*)&QEs[rr * ESTR + cc]       = make_float2(ea[nb * 4],     ea[nb * 4 + 1]);
            *(float2*)&QEs[(rr + 8) * ESTR + cc] = make_float2(ea[nb * 4 + 2], ea[nb * 4 + 3]);
        }
        #pragma unroll
        for (int z = 0; z < 32; z++) ea[z] = 0.f;
        #pragma unroll
        for (int k0 = 0; k0 < 8; k0++) {
            unsigned a[4];
            int ar = (mrow + lq) * SSTR + k0 * 8 + lr;
            a[0] = __float_as_uint(Ks[ar]);
            a[1] = __float_as_uint(Ks[ar + 8 * SSTR]);
            a[2] = __float_as_uint(Ks[ar + 4]);
            a[3] = __float_as_uint(Ks[ar + 8 * SSTR + 4]);
            #pragma unroll
            for (int nb = 0; nb < 8; nb++) {
                unsigned bf[2];
                int br = (nh + nb * 8 + lq) * SSTR + k0 * 8 + lr;
                bf[0] = __float_as_uint(Es[br]);
                bf[1] = __float_as_uint(Es[br + 4]);
                mma8(ea + nb * 4, a, bf);
            }
        }
        #pragma unroll
        for (int nb = 0; nb < 8; nb++) {
            int rr = mrow + lq;
            int cc = nh + nb * 8 + lr * 2;
            *(float2*)&KEs[rr * ESTR + cc]       = make_float2(ea[nb * 4],     ea[nb * 4 + 1]);
            *(float2*)&KEs[(rr + 8) * ESTR + cc] = make_float2(ea[nb * 4 + 2], ea[nb * 4 + 3]);
        }
    }

    // ---- B fragments (K tile) resident in registers ---------------------
    unsigned Bf[8][4][2];
    #pragma unroll
    for (int k0 = 0; k0 < 8; k0++)
        #pragma unroll
        for (int nb = 0; nb < 4; nb++) {
            int br = (ncol + nb * 8 + lq) * SSTR + k0 * 8 + lr;
            Bf[k0][nb][0] = __float_as_uint(Ks[br]);
            Bf[k0][nb][1] = __float_as_uint(Ks[br + 4]);
        }

    // ---- qk GEMM into S, pre-scaled by 0.125 ----------------------------
    float S[16];
    #pragma unroll
    for (int z = 0; z < 16; z++) S[z] = 0.f;
    #pragma unroll
    for (int k0 = 0; k0 < 8; k0++) {
        unsigned a[4];
        int ar = (mrow + lq) * SSTR + k0 * 8 + lr;
        a[0] = __float_as_uint(Qs[ar]);
        a[1] = __float_as_uint(Qs[ar + 8 * SSTR]);
        a[2] = __float_as_uint(Qs[ar + 4]);
        a[3] = __float_as_uint(Qs[ar + 8 * SSTR + 4]);
        #pragma unroll
        for (int nb = 0; nb < 4; nb++) mma8(S + nb * 4, a, Bf[k0][nb]);
    }
    #pragma unroll
    for (int z = 0; z < 16; z++) S[z] *= 0.125f;

    // ---- struct0 prefetch, abs biases -----------------------------------
    float2 streg[8];
    #pragma unroll
    for (int nb = 0; nb < 4; nb++)
        #pragma unroll
        for (int hf = 0; hf < 2; hf++) {
            int rowl = mrow + lq + hf * 8;
            int colg = ncol + nb * 8 + lr * 2;
            streg[nb * 2 + hf] = *(const float2*)&structm[
                ((size_t)b * LL + l0 + rowl) * LL + r0 + colg];
        }
    float absv[5];
    #pragma unroll
    for (int i = 0; i < 5; i++) absv[i] = abs_bias[i * HH + h];

    // ---- 5 SSAN GEMMs, double-buffered QW tiles, struct fold-in ---------
    #pragma unroll
    for (int i = 0; i < 5; i++) {
        float* wb = (i & 1) ? Wb1 : Wb0;
        #pragma unroll
        for (int c = 0; c < 4; c++) {
            float4 v = wreg[c];
            float4 o = {f2tff(v.x), f2tff(v.y), f2tff(v.z), f2tff(v.w)};
            *(float4*)&wb[lt * SSTR + d16 + c * 4] = o;
        }
        if (i < 4) {
            const float* nwb = g_qw + ((size_t)((i + 1) * BB + b) * HH + h) * LL * DHH;
            #pragma unroll
            for (int c = 0; c < 4; c++)
                wreg[c] = *(const float4*)&nwb[(l0 + lt) * DHH + d16 + c * 4];
        }
        __syncthreads();

        float Tt[16];
        #pragma unroll
        for (int z = 0; z < 16; z++) Tt[z] = 0.f;
        #pragma unroll
        for (int k0 = 0; k0 < 8; k0++) {
            unsigned a[4];
            int ar = (mrow + lq) * SSTR + k0 * 8 + lr;
            a[0] = __float_as_uint(wb[ar]);
            a[1] = __float_as_uint(wb[ar + 8 * SSTR]);
            a[2] = __float_as_uint(wb[ar + 4]);
            a[3] = __float_as_uint(wb[ar + 8 * SSTR + 4]);
            #pragma unroll
            for (int nb = 0; nb < 4; nb++) mma8(Tt + nb * 4, a, Bf[k0][nb]);
        }
        #pragma unroll
        for (int nb = 0; nb < 4; nb++)
            #pragma unroll
            for (int hf = 0; hf < 2; hf++) {
                int ci = nb * 4 + hf * 2;
                float2 st = streg[nb * 2 + hf];
                S[ci]     += (Tt[ci]     + absv[i]) * st.x;
                S[ci + 1] += (Tt[ci + 1] + absv[i]) * st.y;
            }
        if (i < 4) {
            #pragma unroll
            for (int nb = 0; nb < 4; nb++)
                #pragma unroll
                for (int hf = 0; hf < 2; hf++) {
                    int rowl = mrow + lq + hf * 8;
                    int colg = ncol + nb * 8 + lr * 2;
                    streg[nb * 2 + hf] = *(const float2*)&structm[
                        ((size_t)((i + 1) * BB + b) * LL + l0 + rowl) * LL + r0 + colg];
                }
        }
    }

    // ---- epilogue: e gather, mask, store --------------------------------
    const float* mrp = amask + b * LL + r0;
    #pragma unroll
    for (int nb = 0; nb < 4; nb++) {
        int colg = ncol + nb * 8 + lr * 2;
        float2 mk = *(const float2*)&mrp[colg];
        #pragma unroll
        for (int hf = 0; hf < 2; hf++) {
            int rowl = mrow + lq + hf * 8;
            int m0i = rowl - colg + 63;
            int ci = nb * 4 + hf * 2;
            float v0 = S[ci]     + (QEs[rowl * ESTR + m0i]     + KEs[colg * ESTR + m0i])           * 0.125f + mk.x;
            float v1 = S[ci + 1] + (QEs[rowl * ESTR + m0i - 1] + KEs[(colg + 1) * ESTR + m0i - 1]) * 0.125f + mk.y;
            *(float2*)&g_s[((size_t)bh * LL + l0 + rowl) * LL + r0 + colg] = make_float2(v0, v1);
        }
    }
}

// ---------------------------------------------------------------------------
// K4: row softmax in place.  grid B*H*L, block 256 (4 elems/thread)
// ---------------------------------------------------------------------------
__global__ __launch_bounds__(256) void softmax_kernel()
{
    __shared__ float red[8];
    const int row = blockIdx.x;
    float* p = g_s + (size_t)row * LL;
    const int tid = threadIdx.x;
    const int lane = tid & 31, wid = tid >> 5;

    float v[4];
    #pragma unroll
    for (int i = 0; i < 4; i++) v[i] = p[tid + i * 256];

    float m = fmaxf(fmaxf(v[0], v[1]), fmaxf(v[2], v[3]));
    #pragma unroll
    for (int off = 16; off > 0; off >>= 1)
        m = fmaxf(m, __shfl_xor_sync(0xffffffffu, m, off));
    if (lane == 0) red[wid] = m;
    __syncthreads();
    float bm = red[0];
    #pragma unroll
    for (int w = 1; w < 8; w++) bm = fmaxf(bm, red[w]);
    __syncthreads();

    float s = 0.f;
    #pragma unroll
    for (int i = 0; i < 4; i++) { v[i] = __expf(v[i] - bm); s += v[i]; }
    #pragma unroll
    for (int off = 16; off > 0; off >>= 1)
        s += __shfl_xor_sync(0xffffffffu, s, off);
    if (lane == 0) red[wid] = s;
    __syncthreads();
    float tot = red[0] + red[1] + red[2] + red[3] + red[4] + red[5] + red[6] + red[7];
    float inv = 1.f / tot;
    #pragma unroll
    for (int i = 0; i < 4; i++) p[tid + i * 256] = v[i] * inv;
}

// ---------------------------------------------------------------------------
// K5: ctx = probs @ V via mma.sync tf32.  grid (16 ltiles, B*H), block 256.
// k-loop over 1024 in 64-chunks, double-buffered SMEM, V transposed at stage.
// ---------------------------------------------------------------------------
__global__ __launch_bounds__(256, 1) void pv_mma_kernel(float* __restrict__ out)
{
    float* Ps0 = s_mem;                  // 64*68 (P tile, [l][k] tf32)
    float* Vs0 = Ps0 + 64 * SSTR;        // 64*68 (V^T tile, [dh][k] tf32)
    float* Ps1 = Vs0 + 64 * SSTR;
    float* Vs1 = Ps1 + 64 * SSTR;

    const int tid = threadIdx.x;
    const int lane = tid & 31, w = tid >> 5;
    const int l0 = blockIdx.x * 64;
    const int bh = blockIdx.y;
    const int b = bh / HH, h = bh % HH;

    const float* pb = g_s + ((size_t)bh * LL + l0) * LL;
    const float* vb = g_v + (size_t)bh * LL * DHH;

    const int lt = tid >> 2;
    const int d16 = (tid & 3) << 4;
    const int mrow = (w & 3) * 16, ncol = (w >> 2) * 32;
    const int lq = lane >> 2, lr = lane & 3;

    float4 preg[4], vreg[4];
    #pragma unroll
    for (int c = 0; c < 4; c++) {
        preg[c] = *(const float4*)&pb[(size_t)lt * LL + d16 + c * 4];
        vreg[c] = *(const float4*)&vb[lt * DHH + d16 + c * 4];
    }

    float acc[16];
    #pragma unroll
    for (int z = 0; z < 16; z++) acc[z] = 0.f;

    #pragma unroll 1
    for (int kc = 0; kc < 16; kc++) {
        float* Ps = (kc & 1) ? Ps1 : Ps0;
        float* Vs = (kc & 1) ? Vs1 : Vs0;
        #pragma unroll
        for (int c = 0; c < 4; c++) {
            float4 v = preg[c];
            float4 o = {f2tff(v.x), f2tff(v.y), f2tff(v.z), f2tff(v.w)};
            *(float4*)&Ps[lt * SSTR + d16 + c * 4] = o;
            float4 vv = vreg[c];
            Vs[(d16 + c * 4 + 0) * SSTR + lt] = f2tff(vv.x);
            Vs[(d16 + c * 4 + 1) * SSTR + lt] = f2tff(vv.y);
            Vs[(d16 + c * 4 + 2) * SSTR + lt] = f2tff(vv.z);
            Vs[(d16 + c * 4 + 3) * SSTR + lt] = f2tff(vv.w);
        }
        if (kc < 15) {
            #pragma unroll
            for (int c = 0; c < 4; c++) {
                preg[c] = *(const float4*)&pb[(size_t)lt * LL + (kc + 1) * 64 + d16 + c * 4];
                vreg[c] = *(const float4*)&vb[((kc + 1) * 64 + lt) * DHH + d16 + c * 4];
            }
        }
        __syncthreads();
        #pragma unroll
        for (int k0 = 0; k0 < 8; k0++) {
            unsigned a[4];
            int ar = (mrow + lq) * SSTR + k0 * 8 + lr;
            a[0] = __float_as_uint(Ps[ar]);
            a[1] = __float_as_uint(Ps[ar + 8 * SSTR]);
            a[2] = __float_as_uint(Ps[ar + 4]);
            a[3] = __float_as_uint(Ps[ar + 8 * SSTR + 4]);
            #pragma unroll
            for (int nb = 0; nb < 4; nb++) {
                unsigned bf[2];
                int br = (ncol + nb * 8 + lq) * SSTR + k0 * 8 + lr;
                bf[0] = __float_as_uint(Vs[br]);
                bf[1] = __float_as_uint(Vs[br + 4]);
                mma8(acc + nb * 4, a, bf);
            }
        }
    }

    #pragma unroll
    for (int nb = 0; nb < 4; nb++) {
        int colg = ncol + nb * 8 + lr * 2;
        int row = mrow + lq;
        *(float2*)&out[((size_t)b * LL + l0 + row) * DD + h * DHH + colg] =
            make_float2(acc[nb * 4], acc[nb * 4 + 1]);
        *(float2*)&out[((size_t)b * LL + l0 + row + 8) * DD + h * DHH + colg] =
            make_float2(acc[nb * 4 + 2], acc[nb * 4 + 3]);
    }
}

// ---------------------------------------------------------------------------
extern "C" void kernel_launch(void* const* d_in, const int* in_sizes, int n_in,
                              void* d_out, int out_size)
{
    (void)in_sizes; (void)n_in; (void)out_size;
    const float* hidden = (const float*)d_in[0];
    const float* amask  = (const float*)d_in[1];
    const float* structm= (const float*)d_in[2];
    const float* Wq = (const float*)d_in[3];
    const float* bq = (const float*)d_in[4];
    const float* Wk = (const float*)d_in[5];
    const float* bk = (const float*)d_in[6];
    const float* Wv = (const float*)d_in[7];
    const float* bv = (const float*)d_in[8];
    const float* dist  = (const float*)d_in[9];
    const float* ssanw = (const float*)d_in[10];
    const float* absb  = (const float*)d_in[11];
    float* out = (float*)d_out;

    // scores smem: Qs+Ks (2*4352) + Es (8704) + Wb (2*4352) + QEs+KEs (2*8448)
    const int SC_SMEM = (2 * 64 * SSTR + 128 * SSTR + 2 * 64 * SSTR + 2 * 64 * ESTR) * 4;
    cudaFuncSetAttribute(scores_mma_kernel,
                         cudaFuncAttributeMaxDynamicSharedMemorySize, SC_SMEM);
    const int PV_SMEM = 4 * 64 * SSTR * 4;
    cudaFuncSetAttribute(pv_mma_kernel,
                         cudaFuncAttributeMaxDynamicSharedMemorySize, PV_SMEM);

    dim3 blk(256);
    proj_kernel<<<dim3(12, 32), blk>>>(hidden, Wq, bq, 0);
    proj_kernel<<<dim3(12, 32), blk>>>(hidden, Wk, bk, 1);
    proj_kernel<<<dim3(12, 32), blk>>>(hidden, Wv, bv, 2);
    qw_kernel<<<dim3(16, HH, 10), blk>>>(ssanw);
    scores_mma_kernel<<<dim3(16, 16, NBH), blk, SC_SMEM>>>(amask, structm, dist, absb);
    softmax_kernel<<<NBH * LL, blk>>>();
    pv_mma_kernel<<<dim3(16, NBH), blk, PV_SMEM>>>(out);
}

// round 8
// speedup vs baseline: 1.0021x; 1.0021x over previous
#include <cuda_runtime.h>
#include <math.h>

#define BB  2
#define HH  12
#define LL  1024
#define DD  768
#define DHH 64
#define NBH (BB*HH)
#define SSTR 68
#define ESTR 132

// Scratch (static __device__ arrays; no allocations anywhere)
__device__ float g_q [NBH*LL*DHH];        //  6.3 MB  [b,h,l,dh]
__device__ float g_k [NBH*LL*DHH];
__device__ float g_v [NBH*LL*DHH];
__device__ float g_qw[5*NBH*LL*DHH];      // 31.5 MB  [i,b,h,l,e]
__device__ float g_s [NBH*LL*LL];         // 100.7 MB [b,h,l,r]

// ---------------------------------------------------------------------------
// tf32 mma helpers
// ---------------------------------------------------------------------------
__device__ __forceinline__ unsigned f2tf(float v) {
    unsigned r; asm("cvt.rna.tf32.f32 %0, %1;" : "=r"(r) : "f"(v)); return r;
}
__device__ __forceinline__ float f2tff(float v) { return __uint_as_float(f2tf(v)); }

__device__ __forceinline__ void mma8(float* c, const unsigned* a, const unsigned* b) {
    asm volatile("mma.sync.aligned.m16n8k8.row.col.f32.tf32.tf32.f32 "
        "{%0,%1,%2,%3}, {%4,%5,%6,%7}, {%8,%9}, {%0,%1,%2,%3};"
        : "+f"(c[0]), "+f"(c[1]), "+f"(c[2]), "+f"(c[3])
        : "r"(a[0]), "r"(a[1]), "r"(a[2]), "r"(a[3]), "r"(b[0]), "r"(b[1]));
}

// ---------------------------------------------------------------------------
// K1: projection  out = X @ W + bias, stored as [B,H,L,DH]  (FFMA, ~40us each)
// ---------------------------------------------------------------------------
__global__ __launch_bounds__(256) void proj_kernel(
    const float* __restrict__ X, const float* __restrict__ W,
    const float* __restrict__ bias, int which)
{
    __shared__ float As[16][68];   // [k][m]
    __shared__ float Bs[16][68];   // [k][n]
    float* outp = (which == 0) ? g_q : (which == 1) ? g_k : g_v;

    const int tid = threadIdx.x;
    const int tx = tid & 15, ty = tid >> 4;
    const int n0 = blockIdx.x * 64;
    const int m0 = blockIdx.y * 64;
    const int a_m = tid >> 2,  a_k4 = (tid & 3) << 2;
    const int b_k = tid >> 4,  b_n4 = (tid & 15) << 2;

    float acc[4][4] = {};
    for (int k0 = 0; k0 < DD; k0 += 16) {
        float4 av = *(const float4*)&X[(m0 + a_m) * DD + k0 + a_k4];
        float4 bv = *(const float4*)&W[(k0 + b_k) * DD + n0 + b_n4];
        __syncthreads();
        As[a_k4 + 0][a_m] = av.x;
        As[a_k4 + 1][a_m] = av.y;
        As[a_k4 + 2][a_m] = av.z;
        As[a_k4 + 3][a_m] = av.w;
        *(float4*)&Bs[b_k][b_n4] = bv;
        __syncthreads();
        #pragma unroll
        for (int kk = 0; kk < 16; kk++) {
            float4 a = *(const float4*)&As[kk][ty << 2];
            float4 b = *(const float4*)&Bs[kk][tx << 2];
            float aa[4] = {a.x, a.y, a.z, a.w};
            float bb[4] = {b.x, b.y, b.z, b.w};
            #pragma unroll
            for (int i = 0; i < 4; i++)
                #pragma unroll
                for (int j = 0; j < 4; j++)
                    acc[i][j] += aa[i] * bb[j];
        }
    }
    const int h = blockIdx.x;              // n-tile index == head (DH==64)
    float bb4[4];
    #pragma unroll
    for (int j = 0; j < 4; j++) bb4[j] = bias[n0 + (tx << 2) + j];
    #pragma unroll
    for (int i = 0; i < 4; i++) {
        int row = m0 + (ty << 2) + i;
        int b = row >> 10, l = row & 1023;
        float4 o;
        o.x = acc[i][0] + bb4[0];
        o.y = acc[i][1] + bb4[1];
        o.z = acc[i][2] + bb4[2];
        o.w = acc[i][3] + bb4[3];
        *(float4*)&outp[((b * HH + h) * LL + l) * DHH + (tx << 2)] = o;
    }
}

// ---------------------------------------------------------------------------
// K2: qw[i,b,h,l,:] = q[b,h,l,:] @ ssan_w[i,h]   (FFMA, 35us)
// ---------------------------------------------------------------------------
__global__ __launch_bounds__(256) void qw_kernel(const float* __restrict__ ssan_w)
{
    __shared__ float qsT[64][68];   // [d][l]
    __shared__ float ws [64][68];   // [d][e]
    const int tid = threadIdx.x;
    const int tx = tid & 15, ty = tid >> 4;
    const int l0 = blockIdx.x * 64;
    const int h  = blockIdx.y;
    const int z  = blockIdx.z;           // i*B + b
    const int ii = z >> 1, b = z & 1;

    const float* qb = g_q + ((b * HH + h) * LL) * DHH;
    const float* wb = ssan_w + (ii * HH + h) * DHH * DHH;

    for (int idx = tid; idx < 1024; idx += 256) {
        int lt = idx >> 4, d4 = (idx & 15) << 2;
        float4 v = *(const float4*)&qb[(l0 + lt) * DHH + d4];
        qsT[d4 + 0][lt] = v.x;
        qsT[d4 + 1][lt] = v.y;
        qsT[d4 + 2][lt] = v.z;
        qsT[d4 + 3][lt] = v.w;
        int d = idx >> 4, e4 = (idx & 15) << 2;
        *(float4*)&ws[d][e4] = *(const float4*)&wb[d * DHH + e4];
    }
    __syncthreads();

    float acc[4][4] = {};
    #pragma unroll 4
    for (int d = 0; d < 64; d++) {
        float4 q = *(const float4*)&qsT[d][ty << 2];
        float4 w = *(const float4*)&ws [d][tx << 2];
        float qq[4] = {q.x, q.y, q.z, q.w};
        float ww[4] = {w.x, w.y, w.z, w.w};
        #pragma unroll
        for (int i = 0; i < 4; i++)
            #pragma unroll
            for (int j = 0; j < 4; j++)
                acc[i][j] += qq[i] * ww[j];
    }
    float* ob = g_qw + (((ii * BB + b) * HH + h) * LL) * DHH;
    #pragma unroll
    for (int i = 0; i < 4; i++) {
        float4 o = {acc[i][0], acc[i][1], acc[i][2], acc[i][3]};
        *(float4*)&ob[(l0 + (ty << 2) + i) * DHH + (tx << 2)] = o;
    }
}

// ---------------------------------------------------------------------------
// K3: fused score assembly via mma.sync tf32.
//   s = (q·k + (q+k)·e[l-r]) / 8 + mask + sum_i (qW_i·k + abs_i) * struct_i
// grid (16 rtiles, 16 ltiles, B*H), block 256 (8 warps), 64x64 output tile.
// e-term via two 64x127x64 band GEMMs into SMEM + diagonal gather.
// ---------------------------------------------------------------------------
extern __shared__ float s_mem[];
__global__ __launch_bounds__(256, 1) void scores_mma_kernel(
    const float* __restrict__ amask, const float* __restrict__ structm,
    const float* __restrict__ dist_emb, const float* __restrict__ abs_bias)
{
    float* Qs  = s_mem;                  // 64*68   (tf32 bits)
    float* Ks  = Qs + 64 * SSTR;         // 64*68
    float* Es  = Ks + 64 * SSTR;         // 128*68  (band, row 127 zero)
    float* Wb0 = Es + 128 * SSTR;        // 64*68
    float* Wb1 = Wb0 + 64 * SSTR;        // 64*68
    float* QEs = Wb1 + 64 * SSTR;        // 64*132  fp32 qe band result
    float* KEs = QEs + 64 * ESTR;        // 64*132  fp32 ke band result

    const int tid = threadIdx.x;
    const int lane = tid & 31, w = tid >> 5;
    const int r0 = blockIdx.x * 64;
    const int l0 = blockIdx.y * 64;
    const int bh = blockIdx.z;
    const int b = bh / HH, h = bh % HH;

    const float* qb = g_q + (size_t)bh * LL * DHH;
    const float* kb = g_k + (size_t)bh * LL * DHH;

    // ---- phase 0: stage Q, K, E band (cvt to tf32), prefetch QW0 --------
    const int lt  = tid >> 2;            // 0..63
    const int d16 = (tid & 3) << 4;      // 0,16,32,48
    const int base_m = l0 - r0 + 960;
    const int er = tid >> 1;             // 0..127
    const int ed = (tid & 1) * 32;

    float4 qreg[4], kreg[4], wreg[4], ereg[8];
    #pragma unroll
    for (int c = 0; c < 4; c++) {
        qreg[c] = *(const float4*)&qb[(l0 + lt) * DHH + d16 + c * 4];
        kreg[c] = *(const float4*)&kb[(r0 + lt) * DHH + d16 + c * 4];
    }
    {
        const float* wb = g_qw + ((size_t)(0 * BB + b) * HH + h) * LL * DHH;
        #pragma unroll
        for (int c = 0; c < 4; c++)
            wreg[c] = *(const float4*)&wb[(l0 + lt) * DHH + d16 + c * 4];
    }
    #pragma unroll
    for (int c = 0; c < 8; c++)
        ereg[c] = (er < 127) ? *(const float4*)&dist_emb[(base_m + er) * DHH + ed + c * 4]
                             : make_float4(0.f, 0.f, 0.f, 0.f);

    #pragma unroll
    for (int c = 0; c < 4; c++) {
        float4 v = qreg[c];
        float4 o = {f2tff(v.x), f2tff(v.y), f2tff(v.z), f2tff(v.w)};
        *(float4*)&Qs[lt * SSTR + d16 + c * 4] = o;
        v = kreg[c];
        float4 o2 = {f2tff(v.x), f2tff(v.y), f2tff(v.z), f2tff(v.w)};
        *(float4*)&Ks[lt * SSTR + d16 + c * 4] = o2;
    }
    #pragma unroll
    for (int c = 0; c < 8; c++) {
        float4 v = ereg[c];
        float4 o = {f2tff(v.x), f2tff(v.y), f2tff(v.z), f2tff(v.w)};
        *(float4*)&Es[er * SSTR + ed + c * 4] = o;
    }
    __syncthreads();

    const int mrow = (w & 3) * 16;       // l sub-tile for this warp
    const int ncol = (w >> 2) * 32;      // r sub-range for main GEMMs
    const int nh   = (w >> 2) * 64;      // band sub-range for e GEMMs
    const int lq = lane >> 2, lr = lane & 3;

    // ---- e-band GEMMs: qe = Q @ E^T, ke = K @ E^T (each 64x128x64) ------
    {
        float ea[32];
        #pragma unroll
        for (int z = 0; z < 32; z++) ea[z] = 0.f;
        #pragma unroll
        for (int k0 = 0; k0 < 8; k0++) {
            unsigned a[4];
            int ar = (mrow + lq) * SSTR + k0 * 8 + lr;
            a[0] = __float_as_uint(Qs[ar]);
            a[1] = __float_as_uint(Qs[ar + 8 * SSTR]);
            a[2] = __float_as_uint(Qs[ar + 4]);
            a[3] = __float_as_uint(Qs[ar + 8 * SSTR + 4]);
            #pragma unroll
            for (int nb = 0; nb < 8; nb++) {
                unsigned bf[2];
                int br = (nh + nb * 8 + lq) * SSTR + k0 * 8 + lr;
                bf[0] = __float_as_uint(Es[br]);
                bf[1] = __float_as_uint(Es[br + 4]);
                mma8(ea + nb * 4, a, bf);
            }
        }
        #pragma unroll
        for (int nb = 0; nb < 8; nb++) {
            int rr = mrow + lq;
            int cc = nh + nb * 8 + lr * 2;
            *(float2*)&QEs[rr * ESTR + cc]       = make_float2(ea[nb * 4],     ea[nb * 4 + 1]);
            *(float2*)&QEs[(rr + 8) * ESTR + cc] = make_float2(ea[nb * 4 + 2], ea[nb * 4 + 3]);
        }
        #pragma unroll
        for (int z = 0; z < 32; z++) ea[z] = 0.f;
        #pragma unroll
        for (int k0 = 0; k0 < 8; k0++) {
            unsigned a[4];
            int ar = (mrow + lq) * SSTR + k0 * 8 + lr;
            a[0] = __float_as_uint(Ks[ar]);
            a[1] = __float_as_uint(Ks[ar + 8 * SSTR]);
            a[2] = __float_as_uint(Ks[ar + 4]);
            a[3] = __float_as_uint(Ks[ar + 8 * SSTR + 4]);
            #pragma unroll
            for (int nb = 0; nb < 8; nb++) {
                unsigned bf[2];
                int br = (nh + nb * 8 + lq) * SSTR + k0 * 8 + lr;
                bf[0] = __float_as_uint(Es[br]);
                bf[1] = __float_as_uint(Es[br + 4]);
                mma8(ea + nb * 4, a, bf);
            }
        }
        #pragma unroll
        for (int nb = 0; nb < 8; nb++) {
            int rr = mrow + lq;
            int cc = nh + nb * 8 + lr * 2;
            *(float2*)&KEs[rr * ESTR + cc]       = make_float2(ea[nb * 4],     ea[nb * 4 + 1]);
            *(float2*)&KEs[(rr + 8) * ESTR + cc] = make_float2(ea[nb * 4 + 2], ea[nb * 4 + 3]);
        }
    }

    // ---- B fragments (K tile) resident in registers ---------------------
    unsigned Bf[8][4][2];
    #pragma unroll
    for (int k0 = 0; k0 < 8; k0++)
        #pragma unroll
        for (int nb = 0; nb < 4; nb++) {
            int br = (ncol + nb * 8 + lq) * SSTR + k0 * 8 + lr;
            Bf[k0][nb][0] = __float_as_uint(Ks[br]);
            Bf[k0][nb][1] = __float_as_uint(Ks[br + 4]);
        }

    // ---- qk GEMM into S, pre-scaled by 0.125 ----------------------------
    float S[16];
    #pragma unroll
    for (int z = 0; z < 16; z++) S[z] = 0.f;
    #pragma unroll
    for (int k0 = 0; k0 < 8; k0++) {
        unsigned a[4];
        int ar = (mrow + lq) * SSTR + k0 * 8 + lr;
        a[0] = __float_as_uint(Qs[ar]);
        a[1] = __float_as_uint(Qs[ar + 8 * SSTR]);
        a[2] = __float_as_uint(Qs[ar + 4]);
        a[3] = __float_as_uint(Qs[ar + 8 * SSTR + 4]);
        #pragma unroll
        for (int nb = 0; nb < 4; nb++) mma8(S + nb * 4, a, Bf[k0][nb]);
    }
    #pragma unroll
    for (int z = 0; z < 16; z++) S[z] *= 0.125f;

    // ---- struct0 prefetch, abs biases -----------------------------------
    float2 streg[8];
    #pragma unroll
    for (int nb = 0; nb < 4; nb++)
        #pragma unroll
        for (int hf = 0; hf < 2; hf++) {
            int rowl = mrow + lq + hf * 8;
            int colg = ncol + nb * 8 + lr * 2;
            streg[nb * 2 + hf] = *(const float2*)&structm[
                ((size_t)b * LL + l0 + rowl) * LL + r0 + colg];
        }
    float absv[5];
    #pragma unroll
    for (int i = 0; i < 5; i++) absv[i] = abs_bias[i * HH + h];

    // ---- 5 SSAN GEMMs, double-buffered QW tiles, struct fold-in ---------
    #pragma unroll
    for (int i = 0; i < 5; i++) {
        float* wb = (i & 1) ? Wb1 : Wb0;
        #pragma unroll
        for (int c = 0; c < 4; c++) {
            float4 v = wreg[c];
            float4 o = {f2tff(v.x), f2tff(v.y), f2tff(v.z), f2tff(v.w)};
            *(float4*)&wb[lt * SSTR + d16 + c * 4] = o;
        }
        if (i < 4) {
            const float* nwb = g_qw + ((size_t)((i + 1) * BB + b) * HH + h) * LL * DHH;
            #pragma unroll
            for (int c = 0; c < 4; c++)
                wreg[c] = *(const float4*)&nwb[(l0 + lt) * DHH + d16 + c * 4];
        }
        __syncthreads();

        float Tt[16];
        #pragma unroll
        for (int z = 0; z < 16; z++) Tt[z] = 0.f;
        #pragma unroll
        for (int k0 = 0; k0 < 8; k0++) {
            unsigned a[4];
            int ar = (mrow + lq) * SSTR + k0 * 8 + lr;
            a[0] = __float_as_uint(wb[ar]);
            a[1] = __float_as_uint(wb[ar + 8 * SSTR]);
            a[2] = __float_as_uint(wb[ar + 4]);
            a[3] = __float_as_uint(wb[ar + 8 * SSTR + 4]);
            #pragma unroll
            for (int nb = 0; nb < 4; nb++) mma8(Tt + nb * 4, a, Bf[k0][nb]);
        }
        #pragma unroll
        for (int nb = 0; nb < 4; nb++)
            #pragma unroll
            for (int hf = 0; hf < 2; hf++) {
                int ci = nb * 4 + hf * 2;
                float2 st = streg[nb * 2 + hf];
                S[ci]     += (Tt[ci]     + absv[i]) * st.x;
                S[ci + 1] += (Tt[ci + 1] + absv[i]) * st.y;
            }
        if (i < 4) {
            #pragma unroll
            for (int nb = 0; nb < 4; nb++)
                #pragma unroll
                for (int hf = 0; hf < 2; hf++) {
                    int rowl = mrow + lq + hf * 8;
                    int colg = ncol + nb * 8 + lr * 2;
                    streg[nb * 2 + hf] = *(const float2*)&structm[
                        ((size_t)((i + 1) * BB + b) * LL + l0 + rowl) * LL + r0 + colg];
                }
        }
    }

    // ---- epilogue: e gather, mask, store --------------------------------
    const float* mrp = amask + b * LL + r0;
    #pragma unroll
    for (int nb = 0; nb < 4; nb++) {
        int colg = ncol + nb * 8 + lr * 2;
        float2 mk = *(const float2*)&mrp[colg];
        #pragma unroll
        for (int hf = 0; hf < 2; hf++) {
            int rowl = mrow + lq + hf * 8;
            int m0i = rowl - colg + 63;
            int ci = nb * 4 + hf * 2;
            float v0 = S[ci]     + (QEs[rowl * ESTR + m0i]     + KEs[colg * ESTR + m0i])           * 0.125f + mk.x;
            float v1 = S[ci + 1] + (QEs[rowl * ESTR + m0i - 1] + KEs[(colg + 1) * ESTR + m0i - 1]) * 0.125f + mk.y;
            *(float2*)&g_s[((size_t)bh * LL + l0 + rowl) * LL + r0 + colg] = make_float2(v0, v1);
        }
    }
}

// ---------------------------------------------------------------------------
// K4: row softmax in place.  grid B*H*L, block 256 (4 elems/thread)
// ---------------------------------------------------------------------------
__global__ __launch_bounds__(256) void softmax_kernel()
{
    __shared__ float red[8];
    const int row = blockIdx.x;
    float* p = g_s + (size_t)row * LL;
    const int tid = threadIdx.x;
    const int lane = tid & 31, wid = tid >> 5;

    float v[4];
    #pragma unroll
    for (int i = 0; i < 4; i++) v[i] = p[tid + i * 256];

    float m = fmaxf(fmaxf(v[0], v[1]), fmaxf(v[2], v[3]));
    #pragma unroll
    for (int off = 16; off > 0; off >>= 1)
        m = fmaxf(m, __shfl_xor_sync(0xffffffffu, m, off));
    if (lane == 0) red[wid] = m;
    __syncthreads();
    float bm = red[0];
    #pragma unroll
    for (int w = 1; w < 8; w++) bm = fmaxf(bm, red[w]);
    __syncthreads();

    float s = 0.f;
    #pragma unroll
    for (int i = 0; i < 4; i++) { v[i] = __expf(v[i] - bm); s += v[i]; }
    #pragma unroll
    for (int off = 16; off > 0; off >>= 1)
        s += __shfl_xor_sync(0xffffffffu, s, off);
    if (lane == 0) red[wid] = s;
    __syncthreads();
    float tot = red[0] + red[1] + red[2] + red[3] + red[4] + red[5] + red[6] + red[7];
    float inv = 1.f / tot;
    #pragma unroll
    for (int i = 0; i < 4; i++) p[tid + i * 256] = v[i] * inv;
}

// ---------------------------------------------------------------------------
// K5: ctx = probs @ V via mma.sync tf32.  grid (16 ltiles, B*H), block 256.
// k-loop over 1024 in 64-chunks, double-buffered SMEM, V transposed at stage.
// ---------------------------------------------------------------------------
__global__ __launch_bounds__(256, 1) void pv_mma_kernel(float* __restrict__ out)
{
    float* Ps0 = s_mem;                  // 64*68 (P tile, [l][k] tf32)
    float* Vs0 = Ps0 + 64 * SSTR;        // 64*68 (V^T tile, [dh][k] tf32)
    float* Ps1 = Vs0 + 64 * SSTR;
    float* Vs1 = Ps1 + 64 * SSTR;

    const int tid = threadIdx.x;
    const int lane = tid & 31, w = tid >> 5;
    const int l0 = blockIdx.x * 64;
    const int bh = blockIdx.y;
    const int b = bh / HH, h = bh % HH;

    const float* pb = g_s + ((size_t)bh * LL + l0) * LL;
    const float* vb = g_v + (size_t)bh * LL * DHH;

    const int lt = tid >> 2;
    const int d16 = (tid & 3) << 4;
    const int mrow = (w & 3) * 16, ncol = (w >> 2) * 32;
    const int lq = lane >> 2, lr = lane & 3;

    float4 preg[4], vreg[4];
    #pragma unroll
    for (int c = 0; c < 4; c++) {
        preg[c] = *(const float4*)&pb[(size_t)lt * LL + d16 + c * 4];
        vreg[c] = *(const float4*)&vb[lt * DHH + d16 + c * 4];
    }

    float acc[16];
    #pragma unroll
    for (int z = 0; z < 16; z++) acc[z] = 0.f;

    #pragma unroll 1
    for (int kc = 0; kc < 16; kc++) {
        float* Ps = (kc & 1) ? Ps1 : Ps0;
        float* Vs = (kc & 1) ? Vs1 : Vs0;
        #pragma unroll
        for (int c = 0; c < 4; c++) {
            float4 v = preg[c];
            float4 o = {f2tff(v.x), f2tff(v.y), f2tff(v.z), f2tff(v.w)};
            *(float4*)&Ps[lt * SSTR + d16 + c * 4] = o;
            float4 vv = vreg[c];
            Vs[(d16 + c * 4 + 0) * SSTR + lt] = f2tff(vv.x);
            Vs[(d16 + c * 4 + 1) * SSTR + lt] = f2tff(vv.y);
            Vs[(d16 + c * 4 + 2) * SSTR + lt] = f2tff(vv.z);
            Vs[(d16 + c * 4 + 3) * SSTR + lt] = f2tff(vv.w);
        }
        if (kc < 15) {
            #pragma unroll
            for (int c = 0; c < 4; c++) {
                preg[c] = *(const float4*)&pb[(size_t)lt * LL + (kc + 1) * 64 + d16 + c * 4];
                vreg[c] = *(const float4*)&vb[((kc + 1) * 64 + lt) * DHH + d16 + c * 4];
            }
        }
        __syncthreads();
        #pragma unroll
        for (int k0 = 0; k0 < 8; k0++) {
            unsigned a[4];
            int ar = (mrow + lq) * SSTR + k0 * 8 + lr;
            a[0] = __float_as_uint(Ps[ar]);
            a[1] = __float_as_uint(Ps[ar + 8 * SSTR]);
            a[2] = __float_as_uint(Ps[ar + 4]);
            a[3] = __float_as_uint(Ps[ar + 8 * SSTR + 4]);
            #pragma unroll
            for (int nb = 0; nb < 4; nb++) {
                unsigned bf[2];
                int br = (ncol + nb * 8 + lq) * SSTR + k0 * 8 + lr;
                bf[0] = __float_as_uint(Vs[br]);
                bf[1] = __float_as_uint(Vs[br + 4]);
                mma8(acc + nb * 4, a, bf);
            }
        }
    }

    #pragma unroll
    for (int nb = 0; nb < 4; nb++) {
        int colg = ncol + nb * 8 + lr * 2;
        int row = mrow + lq;
        *(float2*)&out[((size_t)b * LL + l0 + row) * DD + h * DHH + colg] =
            make_float2(acc[nb * 4], acc[nb * 4 + 1]);
        *(float2*)&out[((size_t)b * LL + l0 + row + 8) * DD + h * DHH + colg] =
            make_float2(acc[nb * 4 + 2], acc[nb * 4 + 3]);
    }
}

// ---------------------------------------------------------------------------
extern "C" void kernel_launch(void* const* d_in, const int* in_sizes, int n_in,
                              void* d_out, int out_size)
{
    (void)in_sizes; (void)n_in; (void)out_size;
    const float* hidden = (const float*)d_in[0];
    const float* amask  = (const float*)d_in[1];
    const float* structm= (const float*)d_in[2];
    const float* Wq = (const float*)d_in[3];
    const float* bq = (const float*)d_in[4];
    const float* Wk = (const float*)d_in[5];
    const float* bk = (const float*)d_in[6];
    const float* Wv = (const float*)d_in[7];
    const float* bv = (const float*)d_in[8];
    const float* dist  = (const float*)d_in[9];
    const float* ssanw = (const float*)d_in[10];
    const float* absb  = (const float*)d_in[11];
    float* out = (float*)d_out;

    // scores smem: Qs+Ks (2*4352) + Es (8704) + Wb (2*4352) + QEs+KEs (2*8448)
    const int SC_SMEM = (2 * 64 * SSTR + 128 * SSTR + 2 * 64 * SSTR + 2 * 64 * ESTR) * 4;
    cudaFuncSetAttribute(scores_mma_kernel,
                         cudaFuncAttributeMaxDynamicSharedMemorySize, SC_SMEM);
    const int PV_SMEM = 4 * 64 * SSTR * 4;
    cudaFuncSetAttribute(pv_mma_kernel,
                         cudaFuncAttributeMaxDynamicSharedMemorySize, PV_SMEM);

    dim3 blk(256);
    proj_kernel<<<dim3(12, 32), blk>>>(hidden, Wq, bq, 0);
    proj_kernel<<<dim3(12, 32), blk>>>(hidden, Wk, bk, 1);
    proj_kernel<<<dim3(12, 32), blk>>>(hidden, Wv, bv, 2);
    qw_kernel<<<dim3(16, HH, 10), blk>>>(ssanw);
    scores_mma_kernel<<<dim3(16, 16, NBH), blk, SC_SMEM>>>(amask, structm, dist, absb);
    softmax_kernel<<<NBH * LL, blk>>>();
    pv_mma_kernel<<<dim3(16, NBH), blk, PV_SMEM>>>(out);
}

// round 9
// speedup vs baseline: 1.0026x; 1.0005x over previous
#include <cuda_runtime.h>
#include <math.h>

#define BB  2
#define HH  12
#define LL  1024
#define DD  768
#define DHH 64
#define NBH (BB*HH)
#define SSTR 68
#define ESTR 132

// Scratch (static __device__ arrays; no allocations anywhere)
__device__ float g_q [NBH*LL*DHH];        //  6.3 MB  [b,h,l,dh]
__device__ float g_k [NBH*LL*DHH];
__device__ float g_v [NBH*LL*DHH];
__device__ float g_qw[5*NBH*LL*DHH];      // 31.5 MB  [i,b,h,l,e]
__device__ float g_s [NBH*LL*LL];         // 100.7 MB [b,h,l,r]

// ---------------------------------------------------------------------------
// tf32 mma helpers
// ---------------------------------------------------------------------------
__device__ __forceinline__ unsigned f2tf(float v) {
    unsigned r; asm("cvt.rna.tf32.f32 %0, %1;" : "=r"(r) : "f"(v)); return r;
}
__device__ __forceinline__ float f2tff(float v) { return __uint_as_float(f2tf(v)); }

__device__ __forceinline__ void mma8(float* c, const unsigned* a, const unsigned* b) {
    asm volatile("mma.sync.aligned.m16n8k8.row.col.f32.tf32.tf32.f32 "
        "{%0,%1,%2,%3}, {%4,%5,%6,%7}, {%8,%9}, {%0,%1,%2,%3};"
        : "+f"(c[0]), "+f"(c[1]), "+f"(c[2]), "+f"(c[3])
        : "r"(a[0]), "r"(a[1]), "r"(a[2]), "r"(a[3]), "r"(b[0]), "r"(b[1]));
}

// ---------------------------------------------------------------------------
// K1: projection  out = X @ W + bias, stored as [B,H,L,DH]  (FFMA, ~40us each)
// ---------------------------------------------------------------------------
__global__ __launch_bounds__(256) void proj_kernel(
    const float* __restrict__ X, const float* __restrict__ W,
    const float* __restrict__ bias, int which)
{
    __shared__ float As[16][68];   // [k][m]
    __shared__ float Bs[16][68];   // [k][n]
    float* outp = (which == 0) ? g_q : (which == 1) ? g_k : g_v;

    const int tid = threadIdx.x;
    const int tx = tid & 15, ty = tid >> 4;
    const int n0 = blockIdx.x * 64;
    const int m0 = blockIdx.y * 64;
    const int a_m = tid >> 2,  a_k4 = (tid & 3) << 2;
    const int b_k = tid >> 4,  b_n4 = (tid & 15) << 2;

    float acc[4][4] = {};
    for (int k0 = 0; k0 < DD; k0 += 16) {
        float4 av = *(const float4*)&X[(m0 + a_m) * DD + k0 + a_k4];
        float4 bv = *(const float4*)&W[(k0 + b_k) * DD + n0 + b_n4];
        __syncthreads();
        As[a_k4 + 0][a_m] = av.x;
        As[a_k4 + 1][a_m] = av.y;
        As[a_k4 + 2][a_m] = av.z;
        As[a_k4 + 3][a_m] = av.w;
        *(float4*)&Bs[b_k][b_n4] = bv;
        __syncthreads();
        #pragma unroll
        for (int kk = 0; kk < 16; kk++) {
            float4 a = *(const float4*)&As[kk][ty << 2];
            float4 b = *(const float4*)&Bs[kk][tx << 2];
            float aa[4] = {a.x, a.y, a.z, a.w};
            float bb[4] = {b.x, b.y, b.z, b.w};
            #pragma unroll
            for (int i = 0; i < 4; i++)
                #pragma unroll
                for (int j = 0; j < 4; j++)
                    acc[i][j] += aa[i] * bb[j];
        }
    }
    const int h = blockIdx.x;              // n-tile index == head (DH==64)
    float bb4[4];
    #pragma unroll
    for (int j = 0; j < 4; j++) bb4[j] = bias[n0 + (tx << 2) + j];
    #pragma unroll
    for (int i = 0; i < 4; i++) {
        int row = m0 + (ty << 2) + i;
        int b = row >> 10, l = row & 1023;
        float4 o;
        o.x = acc[i][0] + bb4[0];
        o.y = acc[i][1] + bb4[1];
        o.z = acc[i][2] + bb4[2];
        o.w = acc[i][3] + bb4[3];
        *(float4*)&outp[((b * HH + h) * LL + l) * DHH + (tx << 2)] = o;
    }
}

// ---------------------------------------------------------------------------
// K2: qw[i,b,h,l,:] = q[b,h,l,:] @ ssan_w[i,h]   (FFMA, 35us)
// ---------------------------------------------------------------------------
__global__ __launch_bounds__(256) void qw_kernel(const float* __restrict__ ssan_w)
{
    __shared__ float qsT[64][68];   // [d][l]
    __shared__ float ws [64][68];   // [d][e]
    const int tid = threadIdx.x;
    const int tx = tid & 15, ty = tid >> 4;
    const int l0 = blockIdx.x * 64;
    const int h  = blockIdx.y;
    const int z  = blockIdx.z;           // i*B + b
    const int ii = z >> 1, b = z & 1;

    const float* qb = g_q + ((b * HH + h) * LL) * DHH;
    const float* wb = ssan_w + (ii * HH + h) * DHH * DHH;

    for (int idx = tid; idx < 1024; idx += 256) {
        int lt = idx >> 4, d4 = (idx & 15) << 2;
        float4 v = *(const float4*)&qb[(l0 + lt) * DHH + d4];
        qsT[d4 + 0][lt] = v.x;
        qsT[d4 + 1][lt] = v.y;
        qsT[d4 + 2][lt] = v.z;
        qsT[d4 + 3][lt] = v.w;
        int d = idx >> 4, e4 = (idx & 15) << 2;
        *(float4*)&ws[d][e4] = *(const float4*)&wb[d * DHH + e4];
    }
    __syncthreads();

    float acc[4][4] = {};
    #pragma unroll 4
    for (int d = 0; d < 64; d++) {
        float4 q = *(const float4*)&qsT[d][ty << 2];
        float4 w = *(const float4*)&ws [d][tx << 2];
        float qq[4] = {q.x, q.y, q.z, q.w};
        float ww[4] = {w.x, w.y, w.z, w.w};
        #pragma unroll
        for (int i = 0; i < 4; i++)
            #pragma unroll
            for (int j = 0; j < 4; j++)
                acc[i][j] += qq[i] * ww[j];
    }
    float* ob = g_qw + (((ii * BB + b) * HH + h) * LL) * DHH;
    #pragma unroll
    for (int i = 0; i < 4; i++) {
        float4 o = {acc[i][0], acc[i][1], acc[i][2], acc[i][3]};
        *(float4*)&ob[(l0 + (ty << 2) + i) * DHH + (tx << 2)] = o;
    }
}

// ---------------------------------------------------------------------------
// K3: fused score assembly via mma.sync tf32.
//   s = (q·k + (q+k)·e[l-r]) / 8 + mask + sum_i (qW_i·k + abs_i) * struct_i
// grid (16 rtiles, 16 ltiles, B*H), block 256 (8 warps), 64x64 output tile.
// e-term via two 64x127x64 band GEMMs into SMEM + diagonal gather.
// ---------------------------------------------------------------------------
extern __shared__ float s_mem[];
__global__ __launch_bounds__(256, 1) void scores_mma_kernel(
    const float* __restrict__ amask, const float* __restrict__ structm,
    const float* __restrict__ dist_emb, const float* __restrict__ abs_bias)
{
    float* Qs  = s_mem;                  // 64*68   (tf32 bits)
    float* Ks  = Qs + 64 * SSTR;         // 64*68
    float* Es  = Ks + 64 * SSTR;         // 128*68  (band, row 127 zero)
    float* Wb0 = Es + 128 * SSTR;        // 64*68
    float* Wb1 = Wb0 + 64 * SSTR;        // 64*68
    float* QEs = Wb1 + 64 * SSTR;        // 64*132  fp32 qe band result
    float* KEs = QEs + 64 * ESTR;        // 64*132  fp32 ke band result

    const int tid = threadIdx.x;
    const int lane = tid & 31, w = tid >> 5;
    const int r0 = blockIdx.x * 64;
    const int l0 = blockIdx.y * 64;
    const int bh = blockIdx.z;
    const int b = bh / HH, h = bh % HH;

    const float* qb = g_q + (size_t)bh * LL * DHH;
    const float* kb = g_k + (size_t)bh * LL * DHH;

    // ---- phase 0: stage Q, K, E band (cvt to tf32), prefetch QW0 --------
    const int lt  = tid >> 2;            // 0..63
    const int d16 = (tid & 3) << 4;      // 0,16,32,48
    const int base_m = l0 - r0 + 960;
    const int er = tid >> 1;             // 0..127
    const int ed = (tid & 1) * 32;

    float4 qreg[4], kreg[4], wreg[4], ereg[8];
    #pragma unroll
    for (int c = 0; c < 4; c++) {
        qreg[c] = *(const float4*)&qb[(l0 + lt) * DHH + d16 + c * 4];
        kreg[c] = *(const float4*)&kb[(r0 + lt) * DHH + d16 + c * 4];
    }
    {
        const float* wb = g_qw + ((size_t)(0 * BB + b) * HH + h) * LL * DHH;
        #pragma unroll
        for (int c = 0; c < 4; c++)
            wreg[c] = *(const float4*)&wb[(l0 + lt) * DHH + d16 + c * 4];
    }
    #pragma unroll
    for (int c = 0; c < 8; c++)
        ereg[c] = (er < 127) ? *(const float4*)&dist_emb[(base_m + er) * DHH + ed + c * 4]
                             : make_float4(0.f, 0.f, 0.f, 0.f);

    #pragma unroll
    for (int c = 0; c < 4; c++) {
        float4 v = qreg[c];
        float4 o = {f2tff(v.x), f2tff(v.y), f2tff(v.z), f2tff(v.w)};
        *(float4*)&Qs[lt * SSTR + d16 + c * 4] = o;
        v = kreg[c];
        float4 o2 = {f2tff(v.x), f2tff(v.y), f2tff(v.z), f2tff(v.w)};
        *(float4*)&Ks[lt * SSTR + d16 + c * 4] = o2;
    }
    #pragma unroll
    for (int c = 0; c < 8; c++) {
        float4 v = ereg[c];
        float4 o = {f2tff(v.x), f2tff(v.y), f2tff(v.z), f2tff(v.w)};
        *(float4*)&Es[er * SSTR + ed + c * 4] = o;
    }
    __syncthreads();

    const int mrow = (w & 3) * 16;       // l sub-tile for this warp
    const int ncol = (w >> 2) * 32;      // r sub-range for main GEMMs
    const int nh   = (w >> 2) * 64;      // band sub-range for e GEMMs
    const int lq = lane >> 2, lr = lane & 3;

    // ---- e-band GEMMs: qe = Q @ E^T, ke = K @ E^T (each 64x128x64) ------
    {
        float ea[32];
        #pragma unroll
        for (int z = 0; z < 32; z++) ea[z] = 0.f;
        #pragma unroll
        for (int k0 = 0; k0 < 8; k0++) {
            unsigned a[4];
            int ar = (mrow + lq) * SSTR + k0 * 8 + lr;
            a[0] = __float_as_uint(Qs[ar]);
            a[1] = __float_as_uint(Qs[ar + 8 * SSTR]);
            a[2] = __float_as_uint(Qs[ar + 4]);
            a[3] = __float_as_uint(Qs[ar + 8 * SSTR + 4]);
            #pragma unroll
            for (int nb = 0; nb < 8; nb++) {
                unsigned bf[2];
                int br = (nh + nb * 8 + lq) * SSTR + k0 * 8 + lr;
                bf[0] = __float_as_uint(Es[br]);
                bf[1] = __float_as_uint(Es[br + 4]);
                mma8(ea + nb * 4, a, bf);
            }
        }
        #pragma unroll
        for (int nb = 0; nb < 8; nb++) {
            int rr = mrow + lq;
            int cc = nh + nb * 8 + lr * 2;
            *(float2*)&QEs[rr * ESTR + cc]       = make_float2(ea[nb * 4],     ea[nb * 4 + 1]);
            *(float2*)&QEs[(rr + 8) * ESTR + cc] = make_float2(ea[nb * 4 + 2], ea[nb * 4 + 3]);
        }
        #pragma unroll
        for (int z = 0; z < 32; z++) ea[z] = 0.f;
        #pragma unroll
        for (int k0 = 0; k0 < 8; k0++) {
            unsigned a[4];
            int ar = (mrow + lq) * SSTR + k0 * 8 + lr;
            a[0] = __float_as_uint(Ks[ar]);
            a[1] = __float_as_uint(Ks[ar + 8 * SSTR]);
            a[2] = __float_as_uint(Ks[ar + 4]);
            a[3] = __float_as_uint(Ks[ar + 8 * SSTR + 4]);
            #pragma unroll
            for (int nb = 0; nb < 8; nb++) {
                unsigned bf[2];
                int br = (nh + nb * 8 + lq) * SSTR + k0 * 8 + lr;
                bf[0] = __float_as_uint(Es[br]);
                bf[1] = __float_as_uint(Es[br + 4]);
                mma8(ea + nb * 4, a, bf);
            }
        }
        #pragma unroll
        for (int nb = 0; nb < 8; nb++) {
            int rr = mrow + lq;
            int cc = nh + nb * 8 + lr * 2;
            *(float2*)&KEs[rr * ESTR + cc]       = make_float2(ea[nb * 4],     ea[nb * 4 + 1]);
            *(float2*)&KEs[(rr + 8) * ESTR + cc] = make_float2(ea[nb * 4 + 2], ea[nb * 4 + 3]);
        }
    }

    // ---- B fragments (K tile) resident in registers ---------------------
    unsigned Bf[8][4][2];
    #pragma unroll
    for (int k0 = 0; k0 < 8; k0++)
        #pragma unroll
        for (int nb = 0; nb < 4; nb++) {
            int br = (ncol + nb * 8 + lq) * SSTR + k0 * 8 + lr;
            Bf[k0][nb][0] = __float_as_uint(Ks[br]);
            Bf[k0][nb][1] = __float_as_uint(Ks[br + 4]);
        }

    // ---- qk GEMM into S, pre-scaled by 0.125 ----------------------------
    float S[16];
    #pragma unroll
    for (int z = 0; z < 16; z++) S[z] = 0.f;
    #pragma unroll
    for (int k0 = 0; k0 < 8; k0++) {
        unsigned a[4];
        int ar = (mrow + lq) * SSTR + k0 * 8 + lr;
        a[0] = __float_as_uint(Qs[ar]);
        a[1] = __float_as_uint(Qs[ar + 8 * SSTR]);
        a[2] = __float_as_uint(Qs[ar + 4]);
        a[3] = __float_as_uint(Qs[ar + 8 * SSTR + 4]);
        #pragma unroll
        for (int nb = 0; nb < 4; nb++) mma8(S + nb * 4, a, Bf[k0][nb]);
    }
    #pragma unroll
    for (int z = 0; z < 16; z++) S[z] *= 0.125f;

    // ---- struct0 prefetch, abs biases -----------------------------------
    float2 streg[8];
    #pragma unroll
    for (int nb = 0; nb < 4; nb++)
        #pragma unroll
        for (int hf = 0; hf < 2; hf++) {
            int rowl = mrow + lq + hf * 8;
            int colg = ncol + nb * 8 + lr * 2;
            streg[nb * 2 + hf] = *(const float2*)&structm[
                ((size_t)b * LL + l0 + rowl) * LL + r0 + colg];
        }
    float absv[5];
    #pragma unroll
    for (int i = 0; i < 5; i++) absv[i] = abs_bias[i * HH + h];

    // ---- 5 SSAN GEMMs, double-buffered QW tiles, struct fold-in ---------
    #pragma unroll
    for (int i = 0; i < 5; i++) {
        float* wb = (i & 1) ? Wb1 : Wb0;
        #pragma unroll
        for (int c = 0; c < 4; c++) {
            float4 v = wreg[c];
            float4 o = {f2tff(v.x), f2tff(v.y), f2tff(v.z), f2tff(v.w)};
            *(float4*)&wb[lt * SSTR + d16 + c * 4] = o;
        }
        if (i < 4) {
            const float* nwb = g_qw + ((size_t)((i + 1) * BB + b) * HH + h) * LL * DHH;
            #pragma unroll
            for (int c = 0; c < 4; c++)
                wreg[c] = *(const float4*)&nwb[(l0 + lt) * DHH + d16 + c * 4];
        }
        __syncthreads();

        float Tt[16];
        #pragma unroll
        for (int z = 0; z < 16; z++) Tt[z] = 0.f;
        #pragma unroll
        for (int k0 = 0; k0 < 8; k0++) {
            unsigned a[4];
            int ar = (mrow + lq) * SSTR + k0 * 8 + lr;
            a[0] = __float_as_uint(wb[ar]);
            a[1] = __float_as_uint(wb[ar + 8 * SSTR]);
            a[2] = __float_as_uint(wb[ar + 4]);
            a[3] = __float_as_uint(wb[ar + 8 * SSTR + 4]);
            #pragma unroll
            for (int nb = 0; nb < 4; nb++) mma8(Tt + nb * 4, a, Bf[k0][nb]);
        }
        #pragma unroll
        for (int nb = 0; nb < 4; nb++)
            #pragma unroll
            for (int hf = 0; hf < 2; hf++) {
                int ci = nb * 4 + hf * 2;
                float2 st = streg[nb * 2 + hf];
                S[ci]     += (Tt[ci]     + absv[i]) * st.x;
                S[ci + 1] += (Tt[ci + 1] + absv[i]) * st.y;
            }
        if (i < 4) {
            #pragma unroll
            for (int nb = 0; nb < 4; nb++)
                #pragma unroll
                for (int hf = 0; hf < 2; hf++) {
                    int rowl = mrow + lq + hf * 8;
                    int colg = ncol + nb * 8 + lr * 2;
                    streg[nb * 2 + hf] = *(const float2*)&structm[
                        ((size_t)((i + 1) * BB + b) * LL + l0 + rowl) * LL + r0 + colg];
                }
        }
    }

    // ---- epilogue: e gather, mask, store --------------------------------
    const float* mrp = amask + b * LL + r0;
    #pragma unroll
    for (int nb = 0; nb < 4; nb++) {
        int colg = ncol + nb * 8 + lr * 2;
        float2 mk = *(const float2*)&mrp[colg];
        #pragma unroll
        for (int hf = 0; hf < 2; hf++) {
            int rowl = mrow + lq + hf * 8;
            int m0i = rowl - colg + 63;
            int ci = nb * 4 + hf * 2;
            float v0 = S[ci]     + (QEs[rowl * ESTR + m0i]     + KEs[colg * ESTR + m0i])           * 0.125f + mk.x;
            float v1 = S[ci + 1] + (QEs[rowl * ESTR + m0i - 1] + KEs[(colg + 1) * ESTR + m0i - 1]) * 0.125f + mk.y;
            *(float2*)&g_s[((size_t)bh * LL + l0 + rowl) * LL + r0 + colg] = make_float2(v0, v1);
        }
    }
}

// ---------------------------------------------------------------------------
// K4: row softmax in place.  grid B*H*L, block 256 (4 elems/thread)
// ---------------------------------------------------------------------------
__global__ __launch_bounds__(256) void softmax_kernel()
{
    __shared__ float red[8];
    const int row = blockIdx.x;
    float* p = g_s + (size_t)row * LL;
    const int tid = threadIdx.x;
    const int lane = tid & 31, wid = tid >> 5;

    float v[4];
    #pragma unroll
    for (int i = 0; i < 4; i++) v[i] = p[tid + i * 256];

    float m = fmaxf(fmaxf(v[0], v[1]), fmaxf(v[2], v[3]));
    #pragma unroll
    for (int off = 16; off > 0; off >>= 1)
        m = fmaxf(m, __shfl_xor_sync(0xffffffffu, m, off));
    if (lane == 0) red[wid] = m;
    __syncthreads();
    float bm = red[0];
    #pragma unroll
    for (int w = 1; w < 8; w++) bm = fmaxf(bm, red[w]);
    __syncthreads();

    float s = 0.f;
    #pragma unroll
    for (int i = 0; i < 4; i++) { v[i] = __expf(v[i] - bm); s += v[i]; }
    #pragma unroll
    for (int off = 16; off > 0; off >>= 1)
        s += __shfl_xor_sync(0xffffffffu, s, off);
    if (lane == 0) red[wid] = s;
    __syncthreads();
    float tot = red[0] + red[1] + red[2] + red[3] + red[4] + red[5] + red[6] + red[7];
    float inv = 1.f / tot;
    #pragma unroll
    for (int i = 0; i < 4; i++) p[tid + i * 256] = v[i] * inv;
}

// ---------------------------------------------------------------------------
// K5: ctx = probs @ V via mma.sync tf32.  grid (16 ltiles, B*H), block 256.
// k-loop over 1024 in 64-chunks, double-buffered SMEM, V transposed at stage.
// ---------------------------------------------------------------------------
__global__ __launch_bounds__(256, 1) void pv_mma_kernel(float* __restrict__ out)
{
    float* Ps0 = s_mem;                  // 64*68 (P tile, [l][k] tf32)
    float* Vs0 = Ps0 + 64 * SSTR;        // 64*68 (V^T tile, [dh][k] tf32)
    float* Ps1 = Vs0 + 64 * SSTR;
    float* Vs1 = Ps1 + 64 * SSTR;

    const int tid = threadIdx.x;
    const int lane = tid & 31, w = tid >> 5;
    const int l0 = blockIdx.x * 64;
    const int bh = blockIdx.y;
    const int b = bh / HH, h = bh % HH;

    const float* pb = g_s + ((size_t)bh * LL + l0) * LL;
    const float* vb = g_v + (size_t)bh * LL * DHH;

    const int lt = tid >> 2;
    const int d16 = (tid & 3) << 4;
    const int mrow = (w & 3) * 16, ncol = (w >> 2) * 32;
    const int lq = lane >> 2, lr = lane & 3;

    float4 preg[4], vreg[4];
    #pragma unroll
    for (int c = 0; c < 4; c++) {
        preg[c] = *(const float4*)&pb[(size_t)lt * LL + d16 + c * 4];
        vreg[c] = *(const float4*)&vb[lt * DHH + d16 + c * 4];
    }

    float acc[16];
    #pragma unroll
    for (int z = 0; z < 16; z++) acc[z] = 0.f;

    #pragma unroll 1
    for (int kc = 0; kc < 16; kc++) {
        float* Ps = (kc & 1) ? Ps1 : Ps0;
        float* Vs = (kc & 1) ? Vs1 : Vs0;
        #pragma unroll
        for (int c = 0; c < 4; c++) {
            float4 v = preg[c];
            float4 o = {f2tff(v.x), f2tff(v.y), f2tff(v.z), f2tff(v.w)};
            *(float4*)&Ps[lt * SSTR + d16 + c * 4] = o;
            float4 vv = vreg[c];
            Vs[(d16 + c * 4 + 0) * SSTR + lt] = f2tff(vv.x);
            Vs[(d16 + c * 4 + 1) * SSTR + lt] = f2tff(vv.y);
            Vs[(d16 + c * 4 + 2) * SSTR + lt] = f2tff(vv.z);
            Vs[(d16 + c * 4 + 3) * SSTR + lt] = f2tff(vv.w);
        }
        if (kc < 15) {
            #pragma unroll
            for (int c = 0; c < 4; c++) {
                preg[c] = *(const float4*)&pb[(size_t)lt * LL + (kc + 1) * 64 + d16 + c * 4];
                vreg[c] = *(const float4*)&vb[((kc + 1) * 64 + lt) * DHH + d16 + c * 4];
            }
        }
        __syncthreads();
        #pragma unroll
        for (int k0 = 0; k0 < 8; k0++) {
            unsigned a[4];
            int ar = (mrow + lq) * SSTR + k0 * 8 + lr;
            a[0] = __float_as_uint(Ps[ar]);
            a[1] = __float_as_uint(Ps[ar + 8 * SSTR]);
            a[2] = __float_as_uint(Ps[ar + 4]);
            a[3] = __float_as_uint(Ps[ar + 8 * SSTR + 4]);
            #pragma unroll
            for (int nb = 0; nb < 4; nb++) {
                unsigned bf[2];
                int br = (ncol + nb * 8 + lq) * SSTR + k0 * 8 + lr;
                bf[0] = __float_as_uint(Vs[br]);
                bf[1] = __float_as_uint(Vs[br + 4]);
                mma8(acc + nb * 4, a, bf);
            }
        }
    }

    #pragma unroll
    for (int nb = 0; nb < 4; nb++) {
        int colg = ncol + nb * 8 + lr * 2;
        int row = mrow + lq;
        *(float2*)&out[((size_t)b * LL + l0 + row) * DD + h * DHH + colg] =
            make_float2(acc[nb * 4], acc[nb * 4 + 1]);
        *(float2*)&out[((size_t)b * LL + l0 + row + 8) * DD + h * DHH + colg] =
            make_float2(acc[nb * 4 + 2], acc[nb * 4 + 3]);
    }
}

// ---------------------------------------------------------------------------
extern "C" void kernel_launch(void* const* d_in, const int* in_sizes, int n_in,
                              void* d_out, int out_size)
{
    (void)in_sizes; (void)n_in; (void)out_size;
    const float* hidden = (const float*)d_in[0];
    const float* amask  = (const float*)d_in[1];
    const float* structm= (const float*)d_in[2];
    const float* Wq = (const float*)d_in[3];
    const float* bq = (const float*)d_in[4];
    const float* Wk = (const float*)d_in[5];
    const float* bk = (const float*)d_in[6];
    const float* Wv = (const float*)d_in[7];
    const float* bv = (const float*)d_in[8];
    const float* dist  = (const float*)d_in[9];
    const float* ssanw = (const float*)d_in[10];
    const float* absb  = (const float*)d_in[11];
    float* out = (float*)d_out;

    // scores smem: Qs+Ks (2*4352) + Es (8704) + Wb (2*4352) + QEs+KEs (2*8448)
    const int SC_SMEM = (2 * 64 * SSTR + 128 * SSTR + 2 * 64 * SSTR + 2 * 64 * ESTR) * 4;
    cudaFuncSetAttribute(scores_mma_kernel,
                         cudaFuncAttributeMaxDynamicSharedMemorySize, SC_SMEM);
    const int PV_SMEM = 4 * 64 * SSTR * 4;
    cudaFuncSetAttribute(pv_mma_kernel,
                         cudaFuncAttributeMaxDynamicSharedMemorySize, PV_SMEM);

    dim3 blk(256);
    proj_kernel<<<dim3(12, 32), blk>>>(hidden, Wq, bq, 0);
    proj_kernel<<<dim3(12, 32), blk>>>(hidden, Wk, bk, 1);
    proj_kernel<<<dim3(12, 32), blk>>>(hidden, Wv, bv, 2);
    qw_kernel<<<dim3(16, HH, 10), blk>>>(ssanw);
    scores_mma_kernel<<<dim3(16, 16, NBH), blk, SC_SMEM>>>(amask, structm, dist, absb);
    softmax_kernel<<<NBH * LL, blk>>>();
    pv_mma_kernel<<<dim3(16, NBH), blk, PV_SMEM>>>(out);
}

// round 10
// speedup vs baseline: 1.0031x; 1.0004x over previous
#include <cuda_runtime.h>
#include <math.h>

#define BB  2
#define HH  12
#define LL  1024
#define DD  768
#define DHH 64
#define NBH (BB*HH)
#define SSTR 68
#define ESTR 132

// Scratch (static __device__ arrays; no allocations anywhere)
__device__ float g_q [NBH*LL*DHH];        //  6.3 MB  [b,h,l,dh]
__device__ float g_k [NBH*LL*DHH];
__device__ float g_v [NBH*LL*DHH];
__device__ float g_qw[5*NBH*LL*DHH];      // 31.5 MB  [i,b,h,l,e]
__device__ float g_s [NBH*LL*LL];         // 100.7 MB [b,h,l,r]

// ---------------------------------------------------------------------------
// tf32 mma helpers
// ---------------------------------------------------------------------------
__device__ __forceinline__ unsigned f2tf(float v) {
    unsigned r; asm("cvt.rna.tf32.f32 %0, %1;" : "=r"(r) : "f"(v)); return r;
}
__device__ __forceinline__ float f2tff(float v) { return __uint_as_float(f2tf(v)); }

__device__ __forceinline__ void mma8(float* c, const unsigned* a, const unsigned* b) {
    asm volatile("mma.sync.aligned.m16n8k8.row.col.f32.tf32.tf32.f32 "
        "{%0,%1,%2,%3}, {%4,%5,%6,%7}, {%8,%9}, {%0,%1,%2,%3};"
        : "+f"(c[0]), "+f"(c[1]), "+f"(c[2]), "+f"(c[3])
        : "r"(a[0]), "r"(a[1]), "r"(a[2]), "r"(a[3]), "r"(b[0]), "r"(b[1]));
}

// ---------------------------------------------------------------------------
// K1: projection  out = X @ W + bias, stored as [B,H,L,DH]  (FFMA, ~40us each)
// ---------------------------------------------------------------------------
__global__ __launch_bounds__(256) void proj_kernel(
    const float* __restrict__ X, const float* __restrict__ W,
    const float* __restrict__ bias, int which)
{
    __shared__ float As[16][68];   // [k][m]
    __shared__ float Bs[16][68];   // [k][n]
    float* outp = (which == 0) ? g_q : (which == 1) ? g_k : g_v;

    const int tid = threadIdx.x;
    const int tx = tid & 15, ty = tid >> 4;
    const int n0 = blockIdx.x * 64;
    const int m0 = blockIdx.y * 64;
    const int a_m = tid >> 2,  a_k4 = (tid & 3) << 2;
    const int b_k = tid >> 4,  b_n4 = (tid & 15) << 2;

    float acc[4][4] = {};
    for (int k0 = 0; k0 < DD; k0 += 16) {
        float4 av = *(const float4*)&X[(m0 + a_m) * DD + k0 + a_k4];
        float4 bv = *(const float4*)&W[(k0 + b_k) * DD + n0 + b_n4];
        __syncthreads();
        As[a_k4 + 0][a_m] = av.x;
        As[a_k4 + 1][a_m] = av.y;
        As[a_k4 + 2][a_m] = av.z;
        As[a_k4 + 3][a_m] = av.w;
        *(float4*)&Bs[b_k][b_n4] = bv;
        __syncthreads();
        #pragma unroll
        for (int kk = 0; kk < 16; kk++) {
            float4 a = *(const float4*)&As[kk][ty << 2];
            float4 b = *(const float4*)&Bs[kk][tx << 2];
            float aa[4] = {a.x, a.y, a.z, a.w};
            float bb[4] = {b.x, b.y, b.z, b.w};
            #pragma unroll
            for (int i = 0; i < 4; i++)
                #pragma unroll
                for (int j = 0; j < 4; j++)
                    acc[i][j] += aa[i] * bb[j];
        }
    }
    const int h = blockIdx.x;              // n-tile index == head (DH==64)
    float bb4[4];
    #pragma unroll
    for (int j = 0; j < 4; j++) bb4[j] = bias[n0 + (tx << 2) + j];
    #pragma unroll
    for (int i = 0; i < 4; i++) {
        int row = m0 + (ty << 2) + i;
        int b = row >> 10, l = row & 1023;
        float4 o;
        o.x = acc[i][0] + bb4[0];
        o.y = acc[i][1] + bb4[1];
        o.z = acc[i][2] + bb4[2];
        o.w = acc[i][3] + bb4[3];
        *(float4*)&outp[((b * HH + h) * LL + l) * DHH + (tx << 2)] = o;
    }
}

// ---------------------------------------------------------------------------
// K2: qw[i,b,h,l,:] = q[b,h,l,:] @ ssan_w[i,h]   (FFMA, 35us)
// ---------------------------------------------------------------------------
__global__ __launch_bounds__(256) void qw_kernel(const float* __restrict__ ssan_w)
{
    __shared__ float qsT[64][68];   // [d][l]
    __shared__ float ws [64][68];   // [d][e]
    const int tid = threadIdx.x;
    const int tx = tid & 15, ty = tid >> 4;
    const int l0 = blockIdx.x * 64;
    const int h  = blockIdx.y;
    const int z  = blockIdx.z;           // i*B + b
    const int ii = z >> 1, b = z & 1;

    const float* qb = g_q + ((b * HH + h) * LL) * DHH;
    const float* wb = ssan_w + (ii * HH + h) * DHH * DHH;

    for (int idx = tid; idx < 1024; idx += 256) {
        int lt = idx >> 4, d4 = (idx & 15) << 2;
        float4 v = *(const float4*)&qb[(l0 + lt) * DHH + d4];
        qsT[d4 + 0][lt] = v.x;
        qsT[d4 + 1][lt] = v.y;
        qsT[d4 + 2][lt] = v.z;
        qsT[d4 + 3][lt] = v.w;
        int d = idx >> 4, e4 = (idx & 15) << 2;
        *(float4*)&ws[d][e4] = *(const float4*)&wb[d * DHH + e4];
    }
    __syncthreads();

    float acc[4][4] = {};
    #pragma unroll 4
    for (int d = 0; d < 64; d++) {
        float4 q = *(const float4*)&qsT[d][ty << 2];
        float4 w = *(const float4*)&ws [d][tx << 2];
        float qq[4] = {q.x, q.y, q.z, q.w};
        float ww[4] = {w.x, w.y, w.z, w.w};
        #pragma unroll
        for (int i = 0; i < 4; i++)
            #pragma unroll
            for (int j = 0; j < 4; j++)
                acc[i][j] += qq[i] * ww[j];
    }
    float* ob = g_qw + (((ii * BB + b) * HH + h) * LL) * DHH;
    #pragma unroll
    for (int i = 0; i < 4; i++) {
        float4 o = {acc[i][0], acc[i][1], acc[i][2], acc[i][3]};
        *(float4*)&ob[(l0 + (ty << 2) + i) * DHH + (tx << 2)] = o;
    }
}

// ---------------------------------------------------------------------------
// K3: fused score assembly via mma.sync tf32.
//   s = (q·k + (q+k)·e[l-r]) / 8 + mask + sum_i (qW_i·k + abs_i) * struct_i
// grid (16 rtiles, 16 ltiles, B*H), block 256 (8 warps), 64x64 output tile.
// e-term via two 64x127x64 band GEMMs into SMEM + diagonal gather.
// ---------------------------------------------------------------------------
extern __shared__ float s_mem[];
__global__ __launch_bounds__(256, 1) void scores_mma_kernel(
    const float* __restrict__ amask, const float* __restrict__ structm,
    const float* __restrict__ dist_emb, const float* __restrict__ abs_bias)
{
    float* Qs  = s_mem;                  // 64*68   (tf32 bits)
    float* Ks  = Qs + 64 * SSTR;         // 64*68
    float* Es  = Ks + 64 * SSTR;         // 128*68  (band, row 127 zero)
    float* Wb0 = Es + 128 * SSTR;        // 64*68
    float* Wb1 = Wb0 + 64 * SSTR;        // 64*68
    float* QEs = Wb1 + 64 * SSTR;        // 64*132  fp32 qe band result
    float* KEs = QEs + 64 * ESTR;        // 64*132  fp32 ke band result

    const int tid = threadIdx.x;
    const int lane = tid & 31, w = tid >> 5;
    const int r0 = blockIdx.x * 64;
    const int l0 = blockIdx.y * 64;
    const int bh = blockIdx.z;
    const int b = bh / HH, h = bh % HH;

    const float* qb = g_q + (size_t)bh * LL * DHH;
    const float* kb = g_k + (size_t)bh * LL * DHH;

    // ---- phase 0: stage Q, K, E band (cvt to tf32), prefetch QW0 --------
    const int lt  = tid >> 2;            // 0..63
    const int d16 = (tid & 3) << 4;      // 0,16,32,48
    const int base_m = l0 - r0 + 960;
    const int er = tid >> 1;             // 0..127
    const int ed = (tid & 1) * 32;

    float4 qreg[4], kreg[4], wreg[4], ereg[8];
    #pragma unroll
    for (int c = 0; c < 4; c++) {
        qreg[c] = *(const float4*)&qb[(l0 + lt) * DHH + d16 + c * 4];
        kreg[c] = *(const float4*)&kb[(r0 + lt) * DHH + d16 + c * 4];
    }
    {
        const float* wb = g_qw + ((size_t)(0 * BB + b) * HH + h) * LL * DHH;
        #pragma unroll
        for (int c = 0; c < 4; c++)
            wreg[c] = *(const float4*)&wb[(l0 + lt) * DHH + d16 + c * 4];
    }
    #pragma unroll
    for (int c = 0; c < 8; c++)
        ereg[c] = (er < 127) ? *(const float4*)&dist_emb[(base_m + er) * DHH + ed + c * 4]
                             : make_float4(0.f, 0.f, 0.f, 0.f);

    #pragma unroll
    for (int c = 0; c < 4; c++) {
        float4 v = qreg[c];
        float4 o = {f2tff(v.x), f2tff(v.y), f2tff(v.z), f2tff(v.w)};
        *(float4*)&Qs[lt * SSTR + d16 + c * 4] = o;
        v = kreg[c];
        float4 o2 = {f2tff(v.x), f2tff(v.y), f2tff(v.z), f2tff(v.w)};
        *(float4*)&Ks[lt * SSTR + d16 + c * 4] = o2;
    }
    #pragma unroll
    for (int c = 0; c < 8; c++) {
        float4 v = ereg[c];
        float4 o = {f2tff(v.x), f2tff(v.y), f2tff(v.z), f2tff(v.w)};
        *(float4*)&Es[er * SSTR + ed + c * 4] = o;
    }
    __syncthreads();

    const int mrow = (w & 3) * 16;       // l sub-tile for this warp
    const int ncol = (w >> 2) * 32;      // r sub-range for main GEMMs
    const int nh   = (w >> 2) * 64;      // band sub-range for e GEMMs
    const int lq = lane >> 2, lr = lane & 3;

    // ---- e-band GEMMs: qe = Q @ E^T, ke = K @ E^T (each 64x128x64) ------
    {
        float ea[32];
        #pragma unroll
        for (int z = 0; z < 32; z++) ea[z] = 0.f;
        #pragma unroll
        for (int k0 = 0; k0 < 8; k0++) {
            unsigned a[4];
            int ar = (mrow + lq) * SSTR + k0 * 8 + lr;
            a[0] = __float_as_uint(Qs[ar]);
            a[1] = __float_as_uint(Qs[ar + 8 * SSTR]);
            a[2] = __float_as_uint(Qs[ar + 4]);
            a[3] = __float_as_uint(Qs[ar + 8 * SSTR + 4]);
            #pragma unroll
            for (int nb = 0; nb < 8; nb++) {
                unsigned bf[2];
                int br = (nh + nb * 8 + lq) * SSTR + k0 * 8 + lr;
                bf[0] = __float_as_uint(Es[br]);
                bf[1] = __float_as_uint(Es[br + 4]);
                mma8(ea + nb * 4, a, bf);
            }
        }
        #pragma unroll
        for (int nb = 0; nb < 8; nb++) {
            int rr = mrow + lq;
            int cc = nh + nb * 8 + lr * 2;
            *(float2*)&QEs[rr * ESTR + cc]       = make_float2(ea[nb * 4],     ea[nb * 4 + 1]);
            *(float2*)&QEs[(rr + 8) * ESTR + cc] = make_float2(ea[nb * 4 + 2], ea[nb * 4 + 3]);
        }
        #pragma unroll
        for (int z = 0; z < 32; z++) ea[z] = 0.f;
        #pragma unroll
        for (int k0 = 0; k0 < 8; k0++) {
            unsigned a[4];
            int ar = (mrow + lq) * SSTR + k0 * 8 + lr;
            a[0] = __float_as_uint(Ks[ar]);
            a[1] = __float_as_uint(Ks[ar + 8 * SSTR]);
            a[2] = __float_as_uint(Ks[ar + 4]);
            a[3] = __float_as_uint(Ks[ar + 8 * SSTR + 4]);
            #pragma unroll
            for (int nb = 0; nb < 8; nb++) {
                unsigned bf[2];
                int br = (nh + nb * 8 + lq) * SSTR + k0 * 8 + lr;
                bf[0] = __float_as_uint(Es[br]);
                bf[1] = __float_as_uint(Es[br + 4]);
                mma8(ea + nb * 4, a, bf);
            }
        }
        #pragma unroll
        for (int nb = 0; nb < 8; nb++) {
            int rr = mrow + lq;
            int cc = nh + nb * 8 + lr * 2;
            *(float2*)&KEs[rr * ESTR + cc]       = make_float2(ea[nb * 4],     ea[nb * 4 + 1]);
            *(float2*)&KEs[(rr + 8) * ESTR + cc] = make_float2(ea[nb * 4 + 2], ea[nb * 4 + 3]);
        }
    }

    // ---- B fragments (K tile) resident in registers ---------------------
    unsigned Bf[8][4][2];
    #pragma unroll
    for (int k0 = 0; k0 < 8; k0++)
        #pragma unroll
        for (int nb = 0; nb < 4; nb++) {
            int br = (ncol + nb * 8 + lq) * SSTR + k0 * 8 + lr;
            Bf[k0][nb][0] = __float_as_uint(Ks[br]);
            Bf[k0][nb][1] = __float_as_uint(Ks[br + 4]);
        }

    // ---- qk GEMM into S, pre-scaled by 0.125 ----------------------------
    float S[16];
    #pragma unroll
    for (int z = 0; z < 16; z++) S[z] = 0.f;
    #pragma unroll
    for (int k0 = 0; k0 < 8; k0++) {
        unsigned a[4];
        int ar = (mrow + lq) * SSTR + k0 * 8 + lr;
        a[0] = __float_as_uint(Qs[ar]);
        a[1] = __float_as_uint(Qs[ar + 8 * SSTR]);
        a[2] = __float_as_uint(Qs[ar + 4]);
        a[3] = __float_as_uint(Qs[ar + 8 * SSTR + 4]);
        #pragma unroll
        for (int nb = 0; nb < 4; nb++) mma8(S + nb * 4, a, Bf[k0][nb]);
    }
    #pragma unroll
    for (int z = 0; z < 16; z++) S[z] *= 0.125f;

    // ---- struct0 prefetch, abs biases -----------------------------------
    float2 streg[8];
    #pragma unroll
    for (int nb = 0; nb < 4; nb++)
        #pragma unroll
        for (int hf = 0; hf < 2; hf++) {
            int rowl = mrow + lq + hf * 8;
            int colg = ncol + nb * 8 + lr * 2;
            streg[nb * 2 + hf] = *(const float2*)&structm[
                ((size_t)b * LL + l0 + rowl) * LL + r0 + colg];
        }
    float absv[5];
    #pragma unroll
    for (int i = 0; i < 5; i++) absv[i] = abs_bias[i * HH + h];

    // ---- 5 SSAN GEMMs, double-buffered QW tiles, struct fold-in ---------
    #pragma unroll
    for (int i = 0; i < 5; i++) {
        float* wb = (i & 1) ? Wb1 : Wb0;
        #pragma unroll
        for (int c = 0; c < 4; c++) {
            float4 v = wreg[c];
            float4 o = {f2tff(v.x), f2tff(v.y), f2tff(v.z), f2tff(v.w)};
            *(float4*)&wb[lt * SSTR + d16 + c * 4] = o;
        }
        if (i < 4) {
            const float* nwb = g_qw + ((size_t)((i + 1) * BB + b) * HH + h) * LL * DHH;
            #pragma unroll
            for (int c = 0; c < 4; c++)
                wreg[c] = *(const float4*)&nwb[(l0 + lt) * DHH + d16 + c * 4];
        }
        __syncthreads();

        float Tt[16];
        #pragma unroll
        for (int z = 0; z < 16; z++) Tt[z] = 0.f;
        #pragma unroll
        for (int k0 = 0; k0 < 8; k0++) {
            unsigned a[4];
            int ar = (mrow + lq) * SSTR + k0 * 8 + lr;
            a[0] = __float_as_uint(wb[ar]);
            a[1] = __float_as_uint(wb[ar + 8 * SSTR]);
            a[2] = __float_as_uint(wb[ar + 4]);
            a[3] = __float_as_uint(wb[ar + 8 * SSTR + 4]);
            #pragma unroll
            for (int nb = 0; nb < 4; nb++) mma8(Tt + nb * 4, a, Bf[k0][nb]);
        }
        #pragma unroll
        for (int nb = 0; nb < 4; nb++)
            #pragma unroll
            for (int hf = 0; hf < 2; hf++) {
                int ci = nb * 4 + hf * 2;
                float2 st = streg[nb * 2 + hf];
                S[ci]     += (Tt[ci]     + absv[i]) * st.x;
                S[ci + 1] += (Tt[ci + 1] + absv[i]) * st.y;
            }
        if (i < 4) {
            #pragma unroll
            for (int nb = 0; nb < 4; nb++)
                #pragma unroll
                for (int hf = 0; hf < 2; hf++) {
                    int rowl = mrow + lq + hf * 8;
                    int colg = ncol + nb * 8 + lr * 2;
                    streg[nb * 2 + hf] = *(const float2*)&structm[
                        ((size_t)((i + 1) * BB + b) * LL + l0 + rowl) * LL + r0 + colg];
                }
        }
    }

    // ---- epilogue: e gather, mask, store --------------------------------
    const float* mrp = amask + b * LL + r0;
    #pragma unroll
    for (int nb = 0; nb < 4; nb++) {
        int colg = ncol + nb * 8 + lr * 2;
        float2 mk = *(const float2*)&mrp[colg];
        #pragma unroll
        for (int hf = 0; hf < 2; hf++) {
            int rowl = mrow + lq + hf * 8;
            int m0i = rowl - colg + 63;
            int ci = nb * 4 + hf * 2;
            float v0 = S[ci]     + (QEs[rowl * ESTR + m0i]     + KEs[colg * ESTR + m0i])           * 0.125f + mk.x;
            float v1 = S[ci + 1] + (QEs[rowl * ESTR + m0i - 1] + KEs[(colg + 1) * ESTR + m0i - 1]) * 0.125f + mk.y;
            *(float2*)&g_s[((size_t)bh * LL + l0 + rowl) * LL + r0 + colg] = make_float2(v0, v1);
        }
    }
}

// ---------------------------------------------------------------------------
// K4: row softmax in place.  grid B*H*L, block 256 (4 elems/thread)
// ---------------------------------------------------------------------------
__global__ __launch_bounds__(256) void softmax_kernel()
{
    __shared__ float red[8];
    const int row = blockIdx.x;
    float* p = g_s + (size_t)row * LL;
    const int tid = threadIdx.x;
    const int lane = tid & 31, wid = tid >> 5;

    float v[4];
    #pragma unroll
    for (int i = 0; i < 4; i++) v[i] = p[tid + i * 256];

    float m = fmaxf(fmaxf(v[0], v[1]), fmaxf(v[2], v[3]));
    #pragma unroll
    for (int off = 16; off > 0; off >>= 1)
        m = fmaxf(m, __shfl_xor_sync(0xffffffffu, m, off));
    if (lane == 0) red[wid] = m;
    __syncthreads();
    float bm = red[0];
    #pragma unroll
    for (int w = 1; w < 8; w++) bm = fmaxf(bm, red[w]);
    __syncthreads();

    float s = 0.f;
    #pragma unroll
    for (int i = 0; i < 4; i++) { v[i] = __expf(v[i] - bm); s += v[i]; }
    #pragma unroll
    for (int off = 16; off > 0; off >>= 1)
        s += __shfl_xor_sync(0xffffffffu, s, off);
    if (lane == 0) red[wid] = s;
    __syncthreads();
    float tot = red[0] + red[1] + red[2] + red[3] + red[4] + red[5] + red[6] + red[7];
    float inv = 1.f / tot;
    #pragma unroll
    for (int i = 0; i < 4; i++) p[tid + i * 256] = v[i] * inv;
}

// ---------------------------------------------------------------------------
// K5: ctx = probs @ V via mma.sync tf32.  grid (16 ltiles, B*H), block 256.
// k-loop over 1024 in 64-chunks, double-buffered SMEM, V transposed at stage.
// ---------------------------------------------------------------------------
__global__ __launch_bounds__(256, 1) void pv_mma_kernel(float* __restrict__ out)
{
    float* Ps0 = s_mem;                  // 64*68 (P tile, [l][k] tf32)
    float* Vs0 = Ps0 + 64 * SSTR;        // 64*68 (V^T tile, [dh][k] tf32)
    float* Ps1 = Vs0 + 64 * SSTR;
    float* Vs1 = Ps1 + 64 * SSTR;

    const int tid = threadIdx.x;
    const int lane = tid & 31, w = tid >> 5;
    const int l0 = blockIdx.x * 64;
    const int bh = blockIdx.y;
    const int b = bh / HH, h = bh % HH;

    const float* pb = g_s + ((size_t)bh * LL + l0) * LL;
    const float* vb = g_v + (size_t)bh * LL * DHH;

    const int lt = tid >> 2;
    const int d16 = (tid & 3) << 4;
    const int mrow = (w & 3) * 16, ncol = (w >> 2) * 32;
    const int lq = lane >> 2, lr = lane & 3;

    float4 preg[4], vreg[4];
    #pragma unroll
    for (int c = 0; c < 4; c++) {
        preg[c] = *(const float4*)&pb[(size_t)lt * LL + d16 + c * 4];
        vreg[c] = *(const float4*)&vb[lt * DHH + d16 + c * 4];
    }

    float acc[16];
    #pragma unroll
    for (int z = 0; z < 16; z++) acc[z] = 0.f;

    #pragma unroll 1
    for (int kc = 0; kc < 16; kc++) {
        float* Ps = (kc & 1) ? Ps1 : Ps0;
        float* Vs = (kc & 1) ? Vs1 : Vs0;
        #pragma unroll
        for (int c = 0; c < 4; c++) {
            float4 v = preg[c];
            float4 o = {f2tff(v.x), f2tff(v.y), f2tff(v.z), f2tff(v.w)};
            *(float4*)&Ps[lt * SSTR + d16 + c * 4] = o;
            float4 vv = vreg[c];
            Vs[(d16 + c * 4 + 0) * SSTR + lt] = f2tff(vv.x);
            Vs[(d16 + c * 4 + 1) * SSTR + lt] = f2tff(vv.y);
            Vs[(d16 + c * 4 + 2) * SSTR + lt] = f2tff(vv.z);
            Vs[(d16 + c * 4 + 3) * SSTR + lt] = f2tff(vv.w);
        }
        if (kc < 15) {
            #pragma unroll
            for (int c = 0; c < 4; c++) {
                preg[c] = *(const float4*)&pb[(size_t)lt * LL + (kc + 1) * 64 + d16 + c * 4];
                vreg[c] = *(const float4*)&vb[((kc + 1) * 64 + lt) * DHH + d16 + c * 4];
            }
        }
        __syncthreads();
        #pragma unroll
        for (int k0 = 0; k0 < 8; k0++) {
            unsigned a[4];
            int ar = (mrow + lq) * SSTR + k0 * 8 + lr;
            a[0] = __float_as_uint(Ps[ar]);
            a[1] = __float_as_uint(Ps[ar + 8 * SSTR]);
            a[2] = __float_as_uint(Ps[ar + 4]);
            a[3] = __float_as_uint(Ps[ar + 8 * SSTR + 4]);
            #pragma unroll
            for (int nb = 0; nb < 4; nb++) {
                unsigned bf[2];
                int br = (ncol + nb * 8 + lq) * SSTR + k0 * 8 + lr;
                bf[0] = __float_as_uint(Vs[br]);
                bf[1] = __float_as_uint(Vs[br + 4]);
                mma8(acc + nb * 4, a, bf);
            }
        }
    }

    #pragma unroll
    for (int nb = 0; nb < 4; nb++) {
        int colg = ncol + nb * 8 + lr * 2;
        int row = mrow + lq;
        *(float2*)&out[((size_t)b * LL + l0 + row) * DD + h * DHH + colg] =
            make_float2(acc[nb * 4], acc[nb * 4 + 1]);
        *(float2*)&out[((size_t)b * LL + l0 + row + 8) * DD + h * DHH + colg] =
            make_float2(acc[nb * 4 + 2], acc[nb * 4 + 3]);
    }
}

// ---------------------------------------------------------------------------
extern "C" void kernel_launch(void* const* d_in, const int* in_sizes, int n_in,
                              void* d_out, int out_size)
{
    (void)in_sizes; (void)n_in; (void)out_size;
    const float* hidden = (const float*)d_in[0];
    const float* amask  = (const float*)d_in[1];
    const float* structm= (const float*)d_in[2];
    const float* Wq = (const float*)d_in[3];
    const float* bq = (const float*)d_in[4];
    const float* Wk = (const float*)d_in[5];
    const float* bk = (const float*)d_in[6];
    const float* Wv = (const float*)d_in[7];
    const float* bv = (const float*)d_in[8];
    const float* dist  = (const float*)d_in[9];
    const float* ssanw = (const float*)d_in[10];
    const float* absb  = (const float*)d_in[11];
    float* out = (float*)d_out;

    // scores smem: Qs+Ks (2*4352) + Es (8704) + Wb (2*4352) + QEs+KEs (2*8448)
    const int SC_SMEM = (2 * 64 * SSTR + 128 * SSTR + 2 * 64 * SSTR + 2 * 64 * ESTR) * 4;
    cudaFuncSetAttribute(scores_mma_kernel,
                         cudaFuncAttributeMaxDynamicSharedMemorySize, SC_SMEM);
    const int PV_SMEM = 4 * 64 * SSTR * 4;
    cudaFuncSetAttribute(pv_mma_kernel,
                         cudaFuncAttributeMaxDynamicSharedMemorySize, PV_SMEM);

    dim3 blk(256);
    proj_kernel<<<dim3(12, 32), blk>>>(hidden, Wq, bq, 0);
    proj_kernel<<<dim3(12, 32), blk>>>(hidden, Wk, bk, 1);
    proj_kernel<<<dim3(12, 32), blk>>>(hidden, Wv, bv, 2);
    qw_kernel<<<dim3(16, HH, 10), blk>>>(ssanw);
    scores_mma_kernel<<<dim3(16, 16, NBH), blk, SC_SMEM>>>(amask, structm, dist, absb);
    softmax_kernel<<<NBH * LL, blk>>>();
    pv_mma_kernel<<<dim3(16, NBH), blk, PV_SMEM>>>(out);
}

// round 11
// speedup vs baseline: 1.0047x; 1.0016x over previous
#include <cuda_runtime.h>
#include <math.h>

#define BB  2
#define HH  12
#define LL  1024
#define DD  768
#define DHH 64
#define NBH (BB*HH)
#define SSTR 68
#define ESTR 132

// Scratch (static __device__ arrays; no allocations anywhere)
__device__ float g_q [NBH*LL*DHH];        //  6.3 MB  [b,h,l,dh]
__device__ float g_k [NBH*LL*DHH];
__device__ float g_v [NBH*LL*DHH];
__device__ float g_qw[5*NBH*LL*DHH];      // 31.5 MB  [i,b,h,l,e]
__device__ float g_s [NBH*LL*LL];         // 100.7 MB [b,h,l,r]

// ---------------------------------------------------------------------------
// tf32 mma helpers
// ---------------------------------------------------------------------------
__device__ __forceinline__ unsigned f2tf(float v) {
    unsigned r; asm("cvt.rna.tf32.f32 %0, %1;" : "=r"(r) : "f"(v)); return r;
}
__device__ __forceinline__ float f2tff(float v) { return __uint_as_float(f2tf(v)); }

__device__ __forceinline__ void mma8(float* c, const unsigned* a, const unsigned* b) {
    asm volatile("mma.sync.aligned.m16n8k8.row.col.f32.tf32.tf32.f32 "
        "{%0,%1,%2,%3}, {%4,%5,%6,%7}, {%8,%9}, {%0,%1,%2,%3};"
        : "+f"(c[0]), "+f"(c[1]), "+f"(c[2]), "+f"(c[3])
        : "r"(a[0]), "r"(a[1]), "r"(a[2]), "r"(a[3]), "r"(b[0]), "r"(b[1]));
}

// ---------------------------------------------------------------------------
// K1: projection  out = X @ W + bias, stored as [B,H,L,DH]  (FFMA, ~40us each)
// ---------------------------------------------------------------------------
__global__ __launch_bounds__(256) void proj_kernel(
    const float* __restrict__ X, const float* __restrict__ W,
    const float* __restrict__ bias, int which)
{
    __shared__ float As[16][68];   // [k][m]
    __shared__ float Bs[16][68];   // [k][n]
    float* outp = (which == 0) ? g_q : (which == 1) ? g_k : g_v;

    const int tid = threadIdx.x;
    const int tx = tid & 15, ty = tid >> 4;
    const int n0 = blockIdx.x * 64;
    const int m0 = blockIdx.y * 64;
    const int a_m = tid >> 2,  a_k4 = (tid & 3) << 2;
    const int b_k = tid >> 4,  b_n4 = (tid & 15) << 2;

    float acc[4][4] = {};
    for (int k0 = 0; k0 < DD; k0 += 16) {
        float4 av = *(const float4*)&X[(m0 + a_m) * DD + k0 + a_k4];
        float4 bv = *(const float4*)&W[(k0 + b_k) * DD + n0 + b_n4];
        __syncthreads();
        As[a_k4 + 0][a_m] = av.x;
        As[a_k4 + 1][a_m] = av.y;
        As[a_k4 + 2][a_m] = av.z;
        As[a_k4 + 3][a_m] = av.w;
        *(float4*)&Bs[b_k][b_n4] = bv;
        __syncthreads();
        #pragma unroll
        for (int kk = 0; kk < 16; kk++) {
            float4 a = *(const float4*)&As[kk][ty << 2];
            float4 b = *(const float4*)&Bs[kk][tx << 2];
            float aa[4] = {a.x, a.y, a.z, a.w};
            float bb[4] = {b.x, b.y, b.z, b.w};
            #pragma unroll
            for (int i = 0; i < 4; i++)
                #pragma unroll
                for (int j = 0; j < 4; j++)
                    acc[i][j] += aa[i] * bb[j];
        }
    }
    const int h = blockIdx.x;              // n-tile index == head (DH==64)
    float bb4[4];
    #pragma unroll
    for (int j = 0; j < 4; j++) bb4[j] = bias[n0 + (tx << 2) + j];
    #pragma unroll
    for (int i = 0; i < 4; i++) {
        int row = m0 + (ty << 2) + i;
        int b = row >> 10, l = row & 1023;
        float4 o;
        o.x = acc[i][0] + bb4[0];
        o.y = acc[i][1] + bb4[1];
        o.z = acc[i][2] + bb4[2];
        o.w = acc[i][3] + bb4[3];
        *(float4*)&outp[((b * HH + h) * LL + l) * DHH + (tx << 2)] = o;
    }
}

// ---------------------------------------------------------------------------
// K2: qw[i,b,h,l,:] = q[b,h,l,:] @ ssan_w[i,h]   (FFMA, 35us)
// ---------------------------------------------------------------------------
__global__ __launch_bounds__(256) void qw_kernel(const float* __restrict__ ssan_w)
{
    __shared__ float qsT[64][68];   // [d][l]
    __shared__ float ws [64][68];   // [d][e]
    const int tid = threadIdx.x;
    const int tx = tid & 15, ty = tid >> 4;
    const int l0 = blockIdx.x * 64;
    const int h  = blockIdx.y;
    const int z  = blockIdx.z;           // i*B + b
    const int ii = z >> 1, b = z & 1;

    const float* qb = g_q + ((b * HH + h) * LL) * DHH;
    const float* wb = ssan_w + (ii * HH + h) * DHH * DHH;

    for (int idx = tid; idx < 1024; idx += 256) {
        int lt = idx >> 4, d4 = (idx & 15) << 2;
        float4 v = *(const float4*)&qb[(l0 + lt) * DHH + d4];
        qsT[d4 + 0][lt] = v.x;
        qsT[d4 + 1][lt] = v.y;
        qsT[d4 + 2][lt] = v.z;
        qsT[d4 + 3][lt] = v.w;
        int d = idx >> 4, e4 = (idx & 15) << 2;
        *(float4*)&ws[d][e4] = *(const float4*)&wb[d * DHH + e4];
    }
    __syncthreads();

    float acc[4][4] = {};
    #pragma unroll 4
    for (int d = 0; d < 64; d++) {
        float4 q = *(const float4*)&qsT[d][ty << 2];
        float4 w = *(const float4*)&ws [d][tx << 2];
        float qq[4] = {q.x, q.y, q.z, q.w};
        float ww[4] = {w.x, w.y, w.z, w.w};
        #pragma unroll
        for (int i = 0; i < 4; i++)
            #pragma unroll
            for (int j = 0; j < 4; j++)
                acc[i][j] += qq[i] * ww[j];
    }
    float* ob = g_qw + (((ii * BB + b) * HH + h) * LL) * DHH;
    #pragma unroll
    for (int i = 0; i < 4; i++) {
        float4 o = {acc[i][0], acc[i][1], acc[i][2], acc[i][3]};
        *(float4*)&ob[(l0 + (ty << 2) + i) * DHH + (tx << 2)] = o;
    }
}

// ---------------------------------------------------------------------------
// K3: fused score assembly via mma.sync tf32.
//   s = (q·k + (q+k)·e[l-r]) / 8 + mask + sum_i (qW_i·k + abs_i) * struct_i
// grid (16 rtiles, 16 ltiles, B*H), block 256 (8 warps), 64x64 output tile.
// e-term via two 64x127x64 band GEMMs into SMEM + diagonal gather.
// ---------------------------------------------------------------------------
extern __shared__ float s_mem[];
__global__ __launch_bounds__(256, 1) void scores_mma_kernel(
    const float* __restrict__ amask, const float* __restrict__ structm,
    const float* __restrict__ dist_emb, const float* __restrict__ abs_bias)
{
    float* Qs  = s_mem;                  // 64*68   (tf32 bits)
    float* Ks  = Qs + 64 * SSTR;         // 64*68
    float* Es  = Ks + 64 * SSTR;         // 128*68  (band, row 127 zero)
    float* Wb0 = Es + 128 * SSTR;        // 64*68
    float* Wb1 = Wb0 + 64 * SSTR;        // 64*68
    float* QEs = Wb1 + 64 * SSTR;        // 64*132  fp32 qe band result
    float* KEs = QEs + 64 * ESTR;        // 64*132  fp32 ke band result

    const int tid = threadIdx.x;
    const int lane = tid & 31, w = tid >> 5;
    const int r0 = blockIdx.x * 64;
    const int l0 = blockIdx.y * 64;
    const int bh = blockIdx.z;
    const int b = bh / HH, h = bh % HH;

    const float* qb = g_q + (size_t)bh * LL * DHH;
    const float* kb = g_k + (size_t)bh * LL * DHH;

    // ---- phase 0: stage Q, K, E band (cvt to tf32), prefetch QW0 --------
    const int lt  = tid >> 2;            // 0..63
    const int d16 = (tid & 3) << 4;      // 0,16,32,48
    const int base_m = l0 - r0 + 960;
    const int er = tid >> 1;             // 0..127
    const int ed = (tid & 1) * 32;

    float4 qreg[4], kreg[4], wreg[4], ereg[8];
    #pragma unroll
    for (int c = 0; c < 4; c++) {
        qreg[c] = *(const float4*)&qb[(l0 + lt) * DHH + d16 + c * 4];
        kreg[c] = *(const float4*)&kb[(r0 + lt) * DHH + d16 + c * 4];
    }
    {
        const float* wb = g_qw + ((size_t)(0 * BB + b) * HH + h) * LL * DHH;
        #pragma unroll
        for (int c = 0; c < 4; c++)
            wreg[c] = *(const float4*)&wb[(l0 + lt) * DHH + d16 + c * 4];
    }
    #pragma unroll
    for (int c = 0; c < 8; c++)
        ereg[c] = (er < 127) ? *(const float4*)&dist_emb[(base_m + er) * DHH + ed + c * 4]
                             : make_float4(0.f, 0.f, 0.f, 0.f);

    #pragma unroll
    for (int c = 0; c < 4; c++) {
        float4 v = qreg[c];
        float4 o = {f2tff(v.x), f2tff(v.y), f2tff(v.z), f2tff(v.w)};
        *(float4*)&Qs[lt * SSTR + d16 + c * 4] = o;
        v = kreg[c];
        float4 o2 = {f2tff(v.x), f2tff(v.y), f2tff(v.z), f2tff(v.w)};
        *(float4*)&Ks[lt * SSTR + d16 + c * 4] = o2;
    }
    #pragma unroll
    for (int c = 0; c < 8; c++) {
        float4 v = ereg[c];
        float4 o = {f2tff(v.x), f2tff(v.y), f2tff(v.z), f2tff(v.w)};
        *(float4*)&Es[er * SSTR + ed + c * 4] = o;
    }
    __syncthreads();

    const int mrow = (w & 3) * 16;       // l sub-tile for this warp
    const int ncol = (w >> 2) * 32;      // r sub-range for main GEMMs
    const int nh   = (w >> 2) * 64;      // band sub-range for e GEMMs
    const int lq = lane >> 2, lr = lane & 3;

    // ---- e-band GEMMs: qe = Q @ E^T, ke = K @ E^T (each 64x128x64) ------
    {
        float ea[32];
        #pragma unroll
        for (int z = 0; z < 32; z++) ea[z] = 0.f;
        #pragma unroll
        for (int k0 = 0; k0 < 8; k0++) {
            unsigned a[4];
            int ar = (mrow + lq) * SSTR + k0 * 8 + lr;
            a[0] = __float_as_uint(Qs[ar]);
            a[1] = __float_as_uint(Qs[ar + 8 * SSTR]);
            a[2] = __float_as_uint(Qs[ar + 4]);
            a[3] = __float_as_uint(Qs[ar + 8 * SSTR + 4]);
            #pragma unroll
            for (int nb = 0; nb < 8; nb++) {
                unsigned bf[2];
                int br = (nh + nb * 8 + lq) * SSTR + k0 * 8 + lr;
                bf[0] = __float_as_uint(Es[br]);
                bf[1] = __float_as_uint(Es[br + 4]);
                mma8(ea + nb * 4, a, bf);
            }
        }
        #pragma unroll
        for (int nb = 0; nb < 8; nb++) {
            int rr = mrow + lq;
            int cc = nh + nb * 8 + lr * 2;
            *(float2*)&QEs[rr * ESTR + cc]       = make_float2(ea[nb * 4],     ea[nb * 4 + 1]);
            *(float2*)&QEs[(rr + 8) * ESTR + cc] = make_float2(ea[nb * 4 + 2], ea[nb * 4 + 3]);
        }
        #pragma unroll
        for (int z = 0; z < 32; z++) ea[z] = 0.f;
        #pragma unroll
        for (int k0 = 0; k0 < 8; k0++) {
            unsigned a[4];
            int ar = (mrow + lq) * SSTR + k0 * 8 + lr;
            a[0] = __float_as_uint(Ks[ar]);
            a[1] = __float_as_uint(Ks[ar + 8 * SSTR]);
            a[2] = __float_as_uint(Ks[ar + 4]);
            a[3] = __float_as_uint(Ks[ar + 8 * SSTR + 4]);
            #pragma unroll
            for (int nb = 0; nb < 8; nb++) {
                unsigned bf[2];
                int br = (nh + nb * 8 + lq) * SSTR + k0 * 8 + lr;
                bf[0] = __float_as_uint(Es[br]);
                bf[1] = __float_as_uint(Es[br + 4]);
                mma8(ea + nb * 4, a, bf);
            }
        }
        #pragma unroll
        for (int nb = 0; nb < 8; nb++) {
            int rr = mrow + lq;
            int cc = nh + nb * 8 + lr * 2;
            *(float2*)&KEs[rr * ESTR + cc]       = make_float2(ea[nb * 4],     ea[nb * 4 + 1]);
            *(float2*)&KEs[(rr + 8) * ESTR + cc] = make_float2(ea[nb * 4 + 2], ea[nb * 4 + 3]);
        }
    }

    // ---- B fragments (K tile) resident in registers ---------------------
    unsigned Bf[8][4][2];
    #pragma unroll
    for (int k0 = 0; k0 < 8; k0++)
        #pragma unroll
        for (int nb = 0; nb < 4; nb++) {
            int br = (ncol + nb * 8 + lq) * SSTR + k0 * 8 + lr;
            Bf[k0][nb][0] = __float_as_uint(Ks[br]);
            Bf[k0][nb][1] = __float_as_uint(Ks[br + 4]);
        }

    // ---- qk GEMM into S, pre-scaled by 0.125 ----------------------------
    float S[16];
    #pragma unroll
    for (int z = 0; z < 16; z++) S[z] = 0.f;
    #pragma unroll
    for (int k0 = 0; k0 < 8; k0++) {
        unsigned a[4];
        int ar = (mrow + lq) * SSTR + k0 * 8 + lr;
        a[0] = __float_as_uint(Qs[ar]);
        a[1] = __float_as_uint(Qs[ar + 8 * SSTR]);
        a[2] = __float_as_uint(Qs[ar + 4]);
        a[3] = __float_as_uint(Qs[ar + 8 * SSTR + 4]);
        #pragma unroll
        for (int nb = 0; nb < 4; nb++) mma8(S + nb * 4, a, Bf[k0][nb]);
    }
    #pragma unroll
    for (int z = 0; z < 16; z++) S[z] *= 0.125f;

    // ---- struct0 prefetch, abs biases -----------------------------------
    float2 streg[8];
    #pragma unroll
    for (int nb = 0; nb < 4; nb++)
        #pragma unroll
        for (int hf = 0; hf < 2; hf++) {
            int rowl = mrow + lq + hf * 8;
            int colg = ncol + nb * 8 + lr * 2;
            streg[nb * 2 + hf] = *(const float2*)&structm[
                ((size_t)b * LL + l0 + rowl) * LL + r0 + colg];
        }
    float absv[5];
    #pragma unroll
    for (int i = 0; i < 5; i++) absv[i] = abs_bias[i * HH + h];

    // ---- 5 SSAN GEMMs, double-buffered QW tiles, struct fold-in ---------
    #pragma unroll
    for (int i = 0; i < 5; i++) {
        float* wb = (i & 1) ? Wb1 : Wb0;
        #pragma unroll
        for (int c = 0; c < 4; c++) {
            float4 v = wreg[c];
            float4 o = {f2tff(v.x), f2tff(v.y), f2tff(v.z), f2tff(v.w)};
            *(float4*)&wb[lt * SSTR + d16 + c * 4] = o;
        }
        if (i < 4) {
            const float* nwb = g_qw + ((size_t)((i + 1) * BB + b) * HH + h) * LL * DHH;
            #pragma unroll
            for (int c = 0; c < 4; c++)
                wreg[c] = *(const float4*)&nwb[(l0 + lt) * DHH + d16 + c * 4];
        }
        __syncthreads();

        float Tt[16];
        #pragma unroll
        for (int z = 0; z < 16; z++) Tt[z] = 0.f;
        #pragma unroll
        for (int k0 = 0; k0 < 8; k0++) {
            unsigned a[4];
            int ar = (mrow + lq) * SSTR + k0 * 8 + lr;
            a[0] = __float_as_uint(wb[ar]);
            a[1] = __float_as_uint(wb[ar + 8 * SSTR]);
            a[2] = __float_as_uint(wb[ar + 4]);
            a[3] = __float_as_uint(wb[ar + 8 * SSTR + 4]);
            #pragma unroll
            for (int nb = 0; nb < 4; nb++) mma8(Tt + nb * 4, a, Bf[k0][nb]);
        }
        #pragma unroll
        for (int nb = 0; nb < 4; nb++)
            #pragma unroll
            for (int hf = 0; hf < 2; hf++) {
                int ci = nb * 4 + hf * 2;
                float2 st = streg[nb * 2 + hf];
                S[ci]     += (Tt[ci]     + absv[i]) * st.x;
                S[ci + 1] += (Tt[ci + 1] + absv[i]) * st.y;
            }
        if (i < 4) {
            #pragma unroll
            for (int nb = 0; nb < 4; nb++)
                #pragma unroll
                for (int hf = 0; hf < 2; hf++) {
                    int rowl = mrow + lq + hf * 8;
                    int colg = ncol + nb * 8 + lr * 2;
                    streg[nb * 2 + hf] = *(const float2*)&structm[
                        ((size_t)((i + 1) * BB + b) * LL + l0 + rowl) * LL + r0 + colg];
                }
        }
    }

    // ---- epilogue: e gather, mask, store --------------------------------
    const float* mrp = amask + b * LL + r0;
    #pragma unroll
    for (int nb = 0; nb < 4; nb++) {
        int colg = ncol + nb * 8 + lr * 2;
        float2 mk = *(const float2*)&mrp[colg];
        #pragma unroll
        for (int hf = 0; hf < 2; hf++) {
            int rowl = mrow + lq + hf * 8;
            int m0i = rowl - colg + 63;
            int ci = nb * 4 + hf * 2;
            float v0 = S[ci]     + (QEs[rowl * ESTR + m0i]     + KEs[colg * ESTR + m0i])           * 0.125f + mk.x;
            float v1 = S[ci + 1] + (QEs[rowl * ESTR + m0i - 1] + KEs[(colg + 1) * ESTR + m0i - 1]) * 0.125f + mk.y;
            *(float2*)&g_s[((size_t)bh * LL + l0 + rowl) * LL + r0 + colg] = make_float2(v0, v1);
        }
    }
}

// ---------------------------------------------------------------------------
// K4: row softmax in place.  grid B*H*L, block 256 (4 elems/thread)
// ---------------------------------------------------------------------------
__global__ __launch_bounds__(256) void softmax_kernel()
{
    __shared__ float red[8];
    const int row = blockIdx.x;
    float* p = g_s + (size_t)row * LL;
    const int tid = threadIdx.x;
    const int lane = tid & 31, wid = tid >> 5;

    float v[4];
    #pragma unroll
    for (int i = 0; i < 4; i++) v[i] = p[tid + i * 256];

    float m = fmaxf(fmaxf(v[0], v[1]), fmaxf(v[2], v[3]));
    #pragma unroll
    for (int off = 16; off > 0; off >>= 1)
        m = fmaxf(m, __shfl_xor_sync(0xffffffffu, m, off));
    if (lane == 0) red[wid] = m;
    __syncthreads();
    float bm = red[0];
    #pragma unroll
    for (int w = 1; w < 8; w++) bm = fmaxf(bm, red[w]);
    __syncthreads();

    float s = 0.f;
    #pragma unroll
    for (int i = 0; i < 4; i++) { v[i] = __expf(v[i] - bm); s += v[i]; }
    #pragma unroll
    for (int off = 16; off > 0; off >>= 1)
        s += __shfl_xor_sync(0xffffffffu, s, off);
    if (lane == 0) red[wid] = s;
    __syncthreads();
    float tot = red[0] + red[1] + red[2] + red[3] + red[4] + red[5] + red[6] + red[7];
    float inv = 1.f / tot;
    #pragma unroll
    for (int i = 0; i < 4; i++) p[tid + i * 256] = v[i] * inv;
}

// ---------------------------------------------------------------------------
// K5: ctx = probs @ V via mma.sync tf32.  grid (16 ltiles, B*H), block 256.
// k-loop over 1024 in 64-chunks, double-buffered SMEM, V transposed at stage.
// ---------------------------------------------------------------------------
__global__ __launch_bounds__(256, 1) void pv_mma_kernel(float* __restrict__ out)
{
    float* Ps0 = s_mem;                  // 64*68 (P tile, [l][k] tf32)
    float* Vs0 = Ps0 + 64 * SSTR;        // 64*68 (V^T tile, [dh][k] tf32)
    float* Ps1 = Vs0 + 64 * SSTR;
    float* Vs1 = Ps1 + 64 * SSTR;

    const int tid = threadIdx.x;
    const int lane = tid & 31, w = tid >> 5;
    const int l0 = blockIdx.x * 64;
    const int bh = blockIdx.y;
    const int b = bh / HH, h = bh % HH;

    const float* pb = g_s + ((size_t)bh * LL + l0) * LL;
    const float* vb = g_v + (size_t)bh * LL * DHH;

    const int lt = tid >> 2;
    const int d16 = (tid & 3) << 4;
    const int mrow = (w & 3) * 16, ncol = (w >> 2) * 32;
    const int lq = lane >> 2, lr = lane & 3;

    float4 preg[4], vreg[4];
    #pragma unroll
    for (int c = 0; c < 4; c++) {
        preg[c] = *(const float4*)&pb[(size_t)lt * LL + d16 + c * 4];
        vreg[c] = *(const float4*)&vb[lt * DHH + d16 + c * 4];
    }

    float acc[16];
    #pragma unroll
    for (int z = 0; z < 16; z++) acc[z] = 0.f;

    #pragma unroll 1
    for (int kc = 0; kc < 16; kc++) {
        float* Ps = (kc & 1) ? Ps1 : Ps0;
        float* Vs = (kc & 1) ? Vs1 : Vs0;
        #pragma unroll
        for (int c = 0; c < 4; c++) {
            float4 v = preg[c];
            float4 o = {f2tff(v.x), f2tff(v.y), f2tff(v.z), f2tff(v.w)};
            *(float4*)&Ps[lt * SSTR + d16 + c * 4] = o;
            float4 vv = vreg[c];
            Vs[(d16 + c * 4 + 0) * SSTR + lt] = f2tff(vv.x);
            Vs[(d16 + c * 4 + 1) * SSTR + lt] = f2tff(vv.y);
            Vs[(d16 + c * 4 + 2) * SSTR + lt] = f2tff(vv.z);
            Vs[(d16 + c * 4 + 3) * SSTR + lt] = f2tff(vv.w);
        }
        if (kc < 15) {
            #pragma unroll
            for (int c = 0; c < 4; c++) {
                preg[c] = *(const float4*)&pb[(size_t)lt * LL + (kc + 1) * 64 + d16 + c * 4];
                vreg[c] = *(const float4*)&vb[((kc + 1) * 64 + lt) * DHH + d16 + c * 4];
            }
        }
        __syncthreads();
        #pragma unroll
        for (int k0 = 0; k0 < 8; k0++) {
            unsigned a[4];
            int ar = (mrow + lq) * SSTR + k0 * 8 + lr;
            a[0] = __float_as_uint(Ps[ar]);
            a[1] = __float_as_uint(Ps[ar + 8 * SSTR]);
            a[2] = __float_as_uint(Ps[ar + 4]);
            a[3] = __float_as_uint(Ps[ar + 8 * SSTR + 4]);
            #pragma unroll
            for (int nb = 0; nb < 4; nb++) {
                unsigned bf[2];
                int br = (ncol + nb * 8 + lq) * SSTR + k0 * 8 + lr;
                bf[0] = __float_as_uint(Vs[br]);
                bf[1] = __float_as_uint(Vs[br + 4]);
                mma8(acc + nb * 4, a, bf);
            }
        }
    }

    #pragma unroll
    for (int nb = 0; nb < 4; nb++) {
        int colg = ncol + nb * 8 + lr * 2;
        int row = mrow + lq;
        *(float2*)&out[((size_t)b * LL + l0 + row) * DD + h * DHH + colg] =
            make_float2(acc[nb * 4], acc[nb * 4 + 1]);
        *(float2*)&out[((size_t)b * LL + l0 + row + 8) * DD + h * DHH + colg] =
            make_float2(acc[nb * 4 + 2], acc[nb * 4 + 3]);
    }
}

// ---------------------------------------------------------------------------
extern "C" void kernel_launch(void* const* d_in, const int* in_sizes, int n_in,
                              void* d_out, int out_size)
{
    (void)in_sizes; (void)n_in; (void)out_size;
    const float* hidden = (const float*)d_in[0];
    const float* amask  = (const float*)d_in[1];
    const float* structm= (const float*)d_in[2];
    const float* Wq = (const float*)d_in[3];
    const float* bq = (const float*)d_in[4];
    const float* Wk = (const float*)d_in[5];
    const float* bk = (const float*)d_in[6];
    const float* Wv = (const float*)d_in[7];
    const float* bv = (const float*)d_in[8];
    const float* dist  = (const float*)d_in[9];
    const float* ssanw = (const float*)d_in[10];
    const float* absb  = (const float*)d_in[11];
    float* out = (float*)d_out;

    // scores smem: Qs+Ks (2*4352) + Es (8704) + Wb (2*4352) + QEs+KEs (2*8448)
    const int SC_SMEM = (2 * 64 * SSTR + 128 * SSTR + 2 * 64 * SSTR + 2 * 64 * ESTR) * 4;
    cudaFuncSetAttribute(scores_mma_kernel,
                         cudaFuncAttributeMaxDynamicSharedMemorySize, SC_SMEM);
    const int PV_SMEM = 4 * 64 * SSTR * 4;
    cudaFuncSetAttribute(pv_mma_kernel,
                         cudaFuncAttributeMaxDynamicSharedMemorySize, PV_SMEM);

    dim3 blk(256);
    proj_kernel<<<dim3(12, 32), blk>>>(hidden, Wq, bq, 0);
    proj_kernel<<<dim3(12, 32), blk>>>(hidden, Wk, bk, 1);
    proj_kernel<<<dim3(12, 32), blk>>>(hidden, Wv, bv, 2);
    qw_kernel<<<dim3(16, HH, 10), blk>>>(ssanw);
    scores_mma_kernel<<<dim3(16, 16, NBH), blk, SC_SMEM>>>(amask, structm, dist, absb);
    softmax_kernel<<<NBH * LL, blk>>>();
    pv_mma_kernel<<<dim3(16, NBH), blk, PV_SMEM>>>(out);
}